// round 15
// baseline (speedup 1.0000x reference)
#include <cuda_runtime.h>
#include <cuda_fp16.h>
#include <math.h>
#include <stdint.h>

// Problem constants
#define LAYERS 2
#define BATCH  4
#define SEQ    1024
#define HID    2048
#define NHEAD  16
#define HDIM   128
#define H3     (3*HID)
#define H4     (4*HID)
#define ROWS   (BATCH*SEQ)
#define NHEADS_TOT (BATCH*NHEAD)
#define EPSV   1e-5f

typedef __half fp16;

// ---------------------------------------------------------------------------
// Scratch (device globals)
// ---------------------------------------------------------------------------
__device__ float g_h   [(size_t)ROWS*HID];
__device__ float g_att [(size_t)ROWS*HID];
__device__ float g_h2  [(size_t)ROWS*HID];
__device__ float g_m2  [(size_t)ROWS*HID];
// fp16 split buffers
__device__ fp16 g_a0 [(size_t)ROWS*HID];
__device__ fp16 g_a1 [(size_t)ROWS*HID];
__device__ fp16 g_qkv0[(size_t)ROWS*H3];
__device__ fp16 g_qkv1[(size_t)ROWS*H3];
__device__ fp16 g_c0 [(size_t)ROWS*HID];
__device__ fp16 g_c1 [(size_t)ROWS*HID];
__device__ fp16 g_m1h[(size_t)ROWS*H4];
__device__ fp16 g_m1l[(size_t)ROWS*H4];
// per-layer fp16 weight buffers (converted on a parallel graph branch)
__device__ fp16 g_wq [(size_t)LAYERS*H3*HID];
__device__ fp16 g_wd [(size_t)LAYERS*HID*HID];
__device__ fp16 g_w1 [(size_t)LAYERS*H4*HID];
__device__ fp16 g_w2 [(size_t)LAYERS*HID*H4];

// ---------------------------------------------------------------------------
// Helpers
// ---------------------------------------------------------------------------
__device__ __forceinline__ uint32_t smem_u32(const void* p) {
    uint32_t a;
    asm("{ .reg .u64 t; cvta.to.shared.u64 t, %1; cvt.u32.u64 %0, t; }"
        : "=r"(a) : "l"(p));
    return a;
}
__device__ __forceinline__ void cp16(uint32_t dst, const void* src) {
    asm volatile("cp.async.cg.shared.global [%0], [%1], 16;"
                 :: "r"(dst), "l"(src) : "memory");
}
__device__ __forceinline__ void cp_commit() {
    asm volatile("cp.async.commit_group;" ::: "memory");
}
template<int N> __device__ __forceinline__ void cp_wait() {
    asm volatile("cp.async.wait_group %0;" :: "n"(N) : "memory");
}
__device__ __forceinline__ void mma16816(float* d, const uint32_t* a, const uint32_t* b) {
    asm volatile(
        "mma.sync.aligned.m16n8k16.row.col.f32.f16.f16.f32 "
        "{%0,%1,%2,%3}, {%4,%5,%6,%7}, {%8,%9}, {%0,%1,%2,%3};"
        : "+f"(d[0]), "+f"(d[1]), "+f"(d[2]), "+f"(d[3])
        : "r"(a[0]), "r"(a[1]), "r"(a[2]), "r"(a[3]), "r"(b[0]), "r"(b[1]));
}
__device__ __forceinline__ void ldsm4(uint32_t* r, uint32_t addr) {
    asm volatile("ldmatrix.sync.aligned.m8n8.x4.shared.b16 {%0,%1,%2,%3}, [%4];"
                 : "=r"(r[0]), "=r"(r[1]), "=r"(r[2]), "=r"(r[3]) : "r"(addr));
}
__device__ __forceinline__ void ldsm4t(uint32_t* r, uint32_t addr) {
    asm volatile("ldmatrix.sync.aligned.m8n8.x4.trans.shared.b16 {%0,%1,%2,%3}, [%4];"
                 : "=r"(r[0]), "=r"(r[1]), "=r"(r[2]), "=r"(r[3]) : "r"(addr));
}
__device__ __forceinline__ float gelu_f(float x) {
    float inner = 0.7978845608028654f * x * (1.0f + 0.044715f * x * x);
    return 0.5f * x * (1.0f + tanhf(inner));
}
__device__ __forceinline__ void st_split2(fp16* H, fp16* L, size_t off, float x, float y) {
    fp16 hx = __float2half_rn(x), hy = __float2half_rn(y);
    fp16 lx = __float2half_rn(x - __half2float(hx));
    fp16 ly = __float2half_rn(y - __half2float(hy));
    *reinterpret_cast<__half2*>(H + off) = __halves2half2(hx, hy);
    *reinterpret_cast<__half2*>(L + off) = __halves2half2(lx, ly);
}
__device__ __forceinline__ void st_hi2(fp16* H, size_t off, float x, float y) {
    *reinterpret_cast<__half2*>(H + off) =
        __halves2half2(__float2half_rn(x), __float2half_rn(y));
}
__device__ __forceinline__ void split_pack(float x, float y, uint32_t& hi, uint32_t& lo) {
    fp16 hx = __float2half_rn(x), hy = __float2half_rn(y);
    fp16 lx = __float2half_rn(x - __half2float(hx));
    fp16 ly = __float2half_rn(y - __half2float(hy));
    __half2 H = __halves2half2(hx, hy), L = __halves2half2(lx, ly);
    hi = *reinterpret_cast<uint32_t*>(&H);
    lo = *reinterpret_cast<uint32_t*>(&L);
}

// ---------------------------------------------------------------------------
// Block reduction (sum)
// ---------------------------------------------------------------------------
__device__ __forceinline__ float blockReduceSum256(float v) {
    __shared__ float sm[8];
    int lane = threadIdx.x & 31, w = threadIdx.x >> 5;
    #pragma unroll
    for (int o = 16; o > 0; o >>= 1) v += __shfl_xor_sync(0xffffffffu, v, o);
    if (lane == 0) sm[w] = v;
    __syncthreads();
    float r = sm[0];
    #pragma unroll
    for (int i = 1; i < 8; i++) r += sm[i];
    __syncthreads();
    return r;
}

// ---------------------------------------------------------------------------
// LayerNorm kernels
// ---------------------------------------------------------------------------
__global__ __launch_bounds__(256) void ln_split_kernel(
    const float* __restrict__ x, const float* __restrict__ gamma,
    const float* __restrict__ beta, fp16* __restrict__ hi, fp16* __restrict__ lo)
{
    const int row = blockIdx.x;
    const int tid = threadIdx.x;
    const float* xr = x + (size_t)row * HID;
    const int cb = tid * 8;

    float v[8];
    *reinterpret_cast<float4*>(v)     = *reinterpret_cast<const float4*>(xr + cb);
    *reinterpret_cast<float4*>(v + 4) = *reinterpret_cast<const float4*>(xr + cb + 4);
    float s = 0.f;
    #pragma unroll
    for (int i = 0; i < 8; i++) s += v[i];
    s = blockReduceSum256(s);
    const float mean = s * (1.0f / HID);

    float q = 0.f;
    #pragma unroll
    for (int i = 0; i < 8; i++) { float d = v[i] - mean; q += d * d; }
    q = blockReduceSum256(q);
    const float rstd = rsqrtf(q * (1.0f / HID) + EPSV);

    const size_t ob = (size_t)row * HID + cb;
    #pragma unroll
    for (int i = 0; i < 8; i += 2) {
        float o0 = (v[i]   - mean) * rstd * gamma[cb+i]   + beta[cb+i];
        float o1 = (v[i+1] - mean) * rstd * gamma[cb+i+1] + beta[cb+i+1];
        st_split2(hi, lo, ob + i, o0, o1);
    }
}

template<int DO_SPLIT>
__global__ __launch_bounds__(256) void ln_res_split_kernel(
    const float* __restrict__ x, const float* __restrict__ res,
    const float* __restrict__ g1, const float* __restrict__ b1,
    const float* __restrict__ g2, const float* __restrict__ b2,
    float* __restrict__ mid, fp16* __restrict__ hi, fp16* __restrict__ lo)
{
    const int row = blockIdx.x;
    const int tid = threadIdx.x;
    const int cb = tid * 8;
    const float* xr = x + (size_t)row * HID;
    const float* rr = res + (size_t)row * HID;

    float v[8];
    *reinterpret_cast<float4*>(v)     = *reinterpret_cast<const float4*>(xr + cb);
    *reinterpret_cast<float4*>(v + 4) = *reinterpret_cast<const float4*>(xr + cb + 4);
    float s = 0.f;
    #pragma unroll
    for (int i = 0; i < 8; i++) s += v[i];
    s = blockReduceSum256(s);
    const float mean = s * (1.0f / HID);

    float q = 0.f;
    #pragma unroll
    for (int i = 0; i < 8; i++) { float d = v[i] - mean; q += d * d; }
    q = blockReduceSum256(q);
    const float rstd = rsqrtf(q * (1.0f / HID) + EPSV);

    float m[8];
    float s2 = 0.f;
    #pragma unroll
    for (int i = 0; i < 8; i++) {
        int c = cb + i;
        m[i] = rr[c] + (v[i] - mean) * rstd * g1[c] + b1[c];
        s2 += m[i];
    }
    float* mr = mid + (size_t)row * HID;
    *reinterpret_cast<float4*>(mr + cb)     = *reinterpret_cast<float4*>(m);
    *reinterpret_cast<float4*>(mr + cb + 4) = *reinterpret_cast<float4*>(m + 4);

    if (DO_SPLIT) {
        s2 = blockReduceSum256(s2);
        const float mean2 = s2 * (1.0f / HID);
        float q2 = 0.f;
        #pragma unroll
        for (int i = 0; i < 8; i++) { float d = m[i] - mean2; q2 += d * d; }
        q2 = blockReduceSum256(q2);
        const float rstd2 = rsqrtf(q2 * (1.0f / HID) + EPSV);

        const size_t ob = (size_t)row * HID + cb;
        #pragma unroll
        for (int i = 0; i < 8; i += 2) {
            int c = cb + i;
            float o0 = (m[i]   - mean2) * rstd2 * g2[c]   + b2[c];
            float o1 = (m[i+1] - mean2) * rstd2 * g2[c+1] + b2[c+1];
            st_split2(hi, lo, ob + i, o0, o1);
        }
    }
}

// ---------------------------------------------------------------------------
// fp32 -> fp16 convert (weights: hi part only)
// ---------------------------------------------------------------------------
__global__ __launch_bounds__(256) void conv_fp32_fp16(
    const float* __restrict__ src, fp16* __restrict__ dst, int n4)
{
    int i = blockIdx.x * 256 + threadIdx.x;
    if (i >= n4) return;
    float4 v = reinterpret_cast<const float4*>(src)[i];
    __half2* dp = reinterpret_cast<__half2*>(dst);
    dp[2*i + 0] = __halves2half2(__float2half_rn(v.x), __float2half_rn(v.y));
    dp[2*i + 1] = __halves2half2(__float2half_rn(v.z), __float2half_rn(v.w));
}

// ---------------------------------------------------------------------------
// Dense 128x128 split-2 fp16 mma body (C = (A0+A1) @ B0^T).
// NON-PERSISTENT: wave transitions overlap via CTA co-residency.
// 4-stage cp.async circular pipeline, compact 64B rows, chunk-XOR swizzle.
// OUT_SPLIT tiles with bn >= lo_limit (K/V outputs): hi-only store AND the
// A1 (activation-lo) term is skipped entirely — mma + loads (evidence R14:
// elementwise ~2^-11 K/V perturbations shift rel_err by ~5e-9).
// ---------------------------------------------------------------------------
#define STAGE_BYTES 24576
#define NSTAGES 4
#define GEMM_SMEM_DYN (NSTAGES*STAGE_BYTES)

template<int GELU, int OUT_SPLIT>
__global__ __launch_bounds__(256, 2) void k_gemm(
    const fp16* __restrict__ A0g, const fp16* __restrict__ A1g,
    const fp16* __restrict__ B0g,
    const float* __restrict__ bias,
    float* __restrict__ Cf, fp16* __restrict__ Ch, fp16* __restrict__ Cl,
    int M, int N, int K, int lo_limit)
{
    extern __shared__ uint32_t smw[];
    const uint32_t smbase = smem_u32(smw);

    const int tid = threadIdx.x;
    const int wid = tid >> 5, lane = tid & 31;
    const int wm = wid & 3, wn = wid >> 2;
    const int g = lane >> 2, c = lane & 3;
    const int bm = blockIdx.y * 128;
    const int bn = blockIdx.x * 128;

    // tile-uniform: K/V output tiles don't need the activation-lo term
    const bool skip_a1 = OUT_SPLIT && (bn >= lo_limit);

    const char* pA0 = (const char*)(A0g + (size_t)bm * K);
    const char* pA1 = (const char*)(A1g + (size_t)bm * K);
    const char* pB0 = (const char*)(B0g + (size_t)bn * K);
    const size_t la = (size_t)K * 2;

    auto load_stage = [&](int it, uint32_t sb) {
        #pragma unroll
        for (int i = 0; i < 6; i++) {
            int idx = tid + i * 256;
            int t  = idx >> 9;
            int r  = (idx >> 2) & 127;
            int ch = idx & 3;
            if (t == 1 && skip_a1) continue;   // A1 unused for this tile
            const char* base = (t == 0) ? pA0 : (t == 1) ? pA1 : pB0;
            cp16(sb + (uint32_t)(t * 8192 + r * 64 + ((ch ^ ((r >> 1) & 3)) << 4)),
                 base + (size_t)r * la + (size_t)it * 64 + ch * 16);
        }
    };

    const int ar   = (lane & 15);
    const int sw_a = (ar >> 1) & 3;
    const int akh  = (lane >> 4) & 1;
    const int br   = (lane & 7) + ((lane & 16) ? 8 : 0);
    const int sw_b = (lane & 7) >> 1;
    const int bkh  = (lane & 8) ? 1 : 0;

    float acc[2][8][4];
    #pragma unroll
    for (int i = 0; i < 2; i++)
        #pragma unroll
        for (int j = 0; j < 8; j++)
            #pragma unroll
            for (int k = 0; k < 4; k++) acc[i][j][k] = 0.f;

    const int nIter = K >> 5;

    #pragma unroll
    for (int s = 0; s < NSTAGES - 1; s++) {
        if (s < nIter) load_stage(s, smbase + (uint32_t)s * STAGE_BYTES);
        cp_commit();
    }

    for (int it = 0; it < nIter; ++it) {
        cp_wait<NSTAGES - 2>();
        __syncthreads();

        if (it + NSTAGES - 1 < nIter)
            load_stage(it + NSTAGES - 1,
                       smbase + (uint32_t)((it + NSTAGES - 1) & (NSTAGES - 1)) * STAGE_BYTES);
        cp_commit();

        const uint32_t sb = smbase + (uint32_t)(it & (NSTAGES - 1)) * STAGE_BYTES;
        #pragma unroll
        for (int ks = 0; ks < 2; ++ks) {
            uint32_t a0r[2][4], a1r[2][4];
            #pragma unroll
            for (int fm = 0; fm < 2; ++fm) {
                uint32_t ao = sb
                    + (uint32_t)((wm * 32 + fm * 16 + ar) * 64
                                 + (((ks * 2 + akh) ^ sw_a) << 4));
                ldsm4(a0r[fm], ao);
                if (!skip_a1) ldsm4(a1r[fm], ao + 8192);
            }
            #pragma unroll
            for (int fn2 = 0; fn2 < 4; ++fn2) {
                uint32_t b0r[4];
                uint32_t bo = sb + 16384
                    + (uint32_t)((wn * 64 + fn2 * 16 + br) * 64
                                 + (((ks * 2 + bkh) ^ sw_b) << 4));
                ldsm4(b0r, bo);
                #pragma unroll
                for (int fm = 0; fm < 2; ++fm) {
                    mma16816(acc[fm][2*fn2],   a0r[fm], b0r);
                    mma16816(acc[fm][2*fn2+1], a0r[fm], b0r + 2);
                    if (!skip_a1) {
                        mma16816(acc[fm][2*fn2],   a1r[fm], b0r);
                        mma16816(acc[fm][2*fn2+1], a1r[fm], b0r + 2);
                    }
                }
            }
        }
    }

    // epilogue
    const bool want_lo = (bn < lo_limit);   // tile-uniform (128-aligned regions)
    #pragma unroll
    for (int fm = 0; fm < 2; ++fm) {
        const int r0 = bm + wm * 32 + fm * 16 + g;
        #pragma unroll
        for (int fn = 0; fn < 8; ++fn) {
            const int col = wn * 64 + fn * 8 + 2 * c;
            float bv0 = __ldg(&bias[bn + col]);
            float bv1 = __ldg(&bias[bn + col + 1]);
            float o0 = acc[fm][fn][0] + bv0;
            float o1 = acc[fm][fn][1] + bv1;
            float o2 = acc[fm][fn][2] + bv0;
            float o3 = acc[fm][fn][3] + bv1;
            if (GELU) { o0 = gelu_f(o0); o1 = gelu_f(o1); o2 = gelu_f(o2); o3 = gelu_f(o3); }
            const size_t off0 = (size_t)r0 * N + bn + col;
            const size_t off1 = (size_t)(r0 + 8) * N + bn + col;
            if (OUT_SPLIT) {
                if (want_lo) {
                    st_split2(Ch, Cl, off0, o0, o1);
                    st_split2(Ch, Cl, off1, o2, o3);
                } else {
                    st_hi2(Ch, off0, o0, o1);
                    st_hi2(Ch, off1, o2, o3);
                }
            } else {
                *reinterpret_cast<float2*>(Cf + off0) = make_float2(o0, o1);
                *reinterpret_cast<float2*>(Cf + off1) = make_float2(o2, o3);
            }
        }
    }
}

// ---------------------------------------------------------------------------
// Fused flash attention (R14 keeper): heavy-first 1D grid, split K/V commit
// groups (V load overlaps QK mma + log2-domain softmax).
// ---------------------------------------------------------------------------
#define ATT_SMEM (3*65536)

__global__ __launch_bounds__(256, 1) void k_attn(
    const fp16* __restrict__ q0, const fp16* __restrict__ q1,
    fp16* __restrict__ c0, fp16* __restrict__ c1)
{
    extern __shared__ char smc[];
    const uint32_t smb = smem_u32(smc);
    const int bid = blockIdx.x;
    const int st = 7 - (bid >> 6);
    const int hd = bid & 63;
    const int b = hd >> 4, n = hd & 15;
    const int tid = threadIdx.x, w = tid >> 5, lane = tid & 31;
    const int g = lane >> 2, c = lane & 3;

    const char* Qg0 = (const char*)(q0 + ((size_t)b*SEQ + (size_t)st*128)*H3 + (size_t)n*HDIM);
    const char* Qg1 = (const char*)(q1 + ((size_t)b*SEQ + (size_t)st*128)*H3 + (size_t)n*HDIM);
    const char* Kg  = (const char*)(q0 + (size_t)b*SEQ*H3 + HID     + (size_t)n*HDIM);
    const char* Vg  = (const char*)(q0 + (size_t)b*SEQ*H3 + 2*HID   + (size_t)n*HDIM);
    const size_t ldq = (size_t)H3 * 2;

    auto load_k = [&](int tt, int buf) {
        const uint32_t kb = smb + 65536u + (uint32_t)buf * 65536u;
        #pragma unroll
        for (int i = 0; i < 8; i++) {
            int idx = tid + i * 256;
            int rr = (idx >> 4) & 127, ch = idx & 15;
            cp16(kb + (uint32_t)(rr * 256 + ((ch ^ (rr & 7)) << 4)),
                 Kg + (size_t)(tt * 128 + rr) * ldq + (size_t)ch * 16);
        }
    };
    auto load_v = [&](int tt, int buf) {
        const uint32_t vb = smb + 65536u + (uint32_t)buf * 65536u + 32768u;
        #pragma unroll
        for (int i = 0; i < 8; i++) {
            int idx = tid + i * 256;
            int rr = (idx >> 4) & 127, ch = idx & 15;
            cp16(vb + (uint32_t)(rr * 256 + ((ch ^ (rr & 7)) << 4)),
                 Vg + (size_t)(tt * 128 + rr) * ldq + (size_t)ch * 16);
        }
    };

    // prologue: group A = Q(hi+lo) + K0; group B = V0
    #pragma unroll
    for (int i = 0; i < 16; i++) {
        int idx = tid + i * 256;
        int sp = idx >> 11, rr = (idx >> 4) & 127, ch = idx & 15;
        cp16(smb + (uint32_t)sp * 32768u
                 + (uint32_t)(rr * 256 + ((ch ^ (rr & 7)) << 4)),
             (sp ? Qg1 : Qg0) + (size_t)rr * ldq + (size_t)ch * 16);
    }
    load_k(0, 0);
    cp_commit();
    load_v(0, 0);
    cp_commit();

    const int ar  = lane & 15;
    const int akh = (lane >> 4) & 1;
    const int br  = (lane & 7) + ((lane & 16) ? 8 : 0);
    const int bkh = (lane & 8) ? 1 : 0;
    const int t0l = lane & 15;
    const int hi16 = (lane & 16) ? 1 : 0;

    float ctx[16][4];
    #pragma unroll
    for (int i = 0; i < 16; i++) { ctx[i][0]=ctx[i][1]=ctx[i][2]=ctx[i][3]=0.f; }
    float mr0 = -1e30f, mr1 = -1e30f, l0 = 0.f, l1 = 0.f;
    const float scale = 0.08838834764831845f * 1.4426950408889634f;  // /sqrt(128) * log2(e)
    const int nt = st + 1;

    for (int tt = 0; tt < nt; tt++) {
        const int buf = tt & 1;
        const bool has_next = (tt + 1 < nt);

        cp_wait<1>();      // retires K_tt
        __syncthreads();

        if (has_next) {
            load_k(tt + 1, buf ^ 1);
            cp_commit();
            load_v(tt + 1, buf ^ 1);
            cp_commit();
        }

        const uint32_t kb = smb + 65536u + (uint32_t)buf * 65536u;

        // ---- S = Q @ K^T (split-2 on Q) ----
        float s[16][4];
        #pragma unroll
        for (int i = 0; i < 16; i++) { s[i][0]=s[i][1]=s[i][2]=s[i][3]=0.f; }
        #pragma unroll
        for (int kf = 0; kf < 8; kf++) {
            uint32_t a0[4], a1[4];
            uint32_t qa = smb + (uint32_t)((w*16 + ar) * 256
                                           + (((kf*2 + akh) ^ (ar & 7)) << 4));
            ldsm4(a0, qa);
            ldsm4(a1, qa + 32768u);
            #pragma unroll
            for (int f2 = 0; f2 < 8; f2++) {
                uint32_t bb[4];
                ldsm4(bb, kb + (uint32_t)((f2*16 + br) * 256
                                          + (((kf*2 + bkh) ^ (br & 7)) << 4)));
                mma16816(s[2*f2],   a0, bb);   mma16816(s[2*f2],   a1, bb);
                mma16816(s[2*f2+1], a0, bb+2); mma16816(s[2*f2+1], a1, bb+2);
            }
        }

        // ---- scale (log2 domain) + causal mask (diagonal tile only) ----
        if (tt == st) {
            const int r0 = w*16 + g, r1 = r0 + 8;
            #pragma unroll
            for (int fn = 0; fn < 16; fn++) {
                int col0 = fn*8 + 2*c;
                s[fn][0] = (col0   > r0) ? -1e30f : s[fn][0]*scale;
                s[fn][1] = (col0+1 > r0) ? -1e30f : s[fn][1]*scale;
                s[fn][2] = (col0   > r1) ? -1e30f : s[fn][2]*scale;
                s[fn][3] = (col0+1 > r1) ? -1e30f : s[fn][3]*scale;
            }
        } else {
            #pragma unroll
            for (int fn = 0; fn < 16; fn++) {
                s[fn][0]*=scale; s[fn][1]*=scale; s[fn][2]*=scale; s[fn][3]*=scale;
            }
        }

        // ---- online softmax in log2 domain ----
        float m0 = -1e30f, m1 = -1e30f;
        #pragma unroll
        for (int fn = 0; fn < 16; fn++) {
            m0 = fmaxf(m0, fmaxf(s[fn][0], s[fn][1]));
            m1 = fmaxf(m1, fmaxf(s[fn][2], s[fn][3]));
        }
        m0 = fmaxf(m0, __shfl_xor_sync(0xffffffffu, m0, 1));
        m0 = fmaxf(m0, __shfl_xor_sync(0xffffffffu, m0, 2));
        m1 = fmaxf(m1, __shfl_xor_sync(0xffffffffu, m1, 1));
        m1 = fmaxf(m1, __shfl_xor_sync(0xffffffffu, m1, 2));
        const float mn0 = fmaxf(mr0, m0), mn1 = fmaxf(mr1, m1);
        const float cr0 = exp2f(mr0 - mn0), cr1 = exp2f(mr1 - mn1);
        mr0 = mn0; mr1 = mn1;
        l0 *= cr0; l1 *= cr1;
        #pragma unroll
        for (int fn = 0; fn < 16; fn++) {
            ctx[fn][0]*=cr0; ctx[fn][1]*=cr0; ctx[fn][2]*=cr1; ctx[fn][3]*=cr1;
        }
        float ps0 = 0.f, ps1 = 0.f;
        #pragma unroll
        for (int fn = 0; fn < 16; fn++) {
            float p0v = exp2f(s[fn][0]-mn0), p1v = exp2f(s[fn][1]-mn0);
            float p2v = exp2f(s[fn][2]-mn1), p3v = exp2f(s[fn][3]-mn1);
            s[fn][0]=p0v; s[fn][1]=p1v; s[fn][2]=p2v; s[fn][3]=p3v;
            ps0 += p0v + p1v; ps1 += p2v + p3v;
        }
        ps0 += __shfl_xor_sync(0xffffffffu, ps0, 1);
        ps0 += __shfl_xor_sync(0xffffffffu, ps0, 2);
        ps1 += __shfl_xor_sync(0xffffffffu, ps1, 1);
        ps1 += __shfl_xor_sync(0xffffffffu, ps1, 2);
        l0 += ps0; l1 += ps1;

        // ---- wait for V_tt only now ----
        if (has_next) cp_wait<2>();
        else          cp_wait<0>();
        __syncthreads();

        // ---- ctx += P @ V (split-2 on P; S C-frags are PV A-frags) ----
        const uint32_t vb = kb + 32768u;
        #pragma unroll
        for (int kf = 0; kf < 8; kf++) {
            uint32_t ahi[4], alo[4];
            split_pack(s[2*kf][0],   s[2*kf][1],   ahi[0], alo[0]);
            split_pack(s[2*kf][2],   s[2*kf][3],   ahi[1], alo[1]);
            split_pack(s[2*kf+1][0], s[2*kf+1][1], ahi[2], alo[2]);
            split_pack(s[2*kf+1][2], s[2*kf+1][3], ahi[3], alo[3]);
            const int t = kf*16 + t0l;
            #pragma unroll
            for (int f2 = 0; f2 < 8; f2++) {
                uint32_t bb[4];
                ldsm4t(bb, vb + (uint32_t)(t * 256
                                           + (((f2*2 + hi16) ^ (t & 7)) << 4)));
                mma16816(ctx[2*f2],   ahi, bb);   mma16816(ctx[2*f2],   alo, bb);
                mma16816(ctx[2*f2+1], ahi, bb+2); mma16816(ctx[2*f2+1], alo, bb+2);
            }
        }
    }

    // ---- epilogue: normalize and store split ctx ----
    const float inv0 = 1.0f / l0, inv1 = 1.0f / l1;
    const size_t base = ((size_t)b*SEQ + (size_t)st*128 + w*16 + g) * HID + (size_t)n*HDIM;
    #pragma unroll
    for (int fn = 0; fn < 16; fn++) {
        const int col = fn*8 + 2*c;
        st_split2(c0, c1, base + col,           ctx[fn][0]*inv0, ctx[fn][1]*inv0);
        st_split2(c0, c1, base + 8*HID + col,   ctx[fn][2]*inv1, ctx[fn][3]*inv1);
    }
}

// ---------------------------------------------------------------------------
// Host side
// ---------------------------------------------------------------------------
static float* symaddrf(const void* sym) {
    void* p = nullptr; cudaGetSymbolAddress(&p, sym); return (float*)p;
}
static fp16* symaddrh(const void* sym) {
    void* p = nullptr; cudaGetSymbolAddress(&p, sym); return (fp16*)p;
}

extern "C" void kernel_launch(void* const* d_in, const int* in_sizes, int n_in,
                              void* d_out, int out_size)
{
    const float* hidden  = (const float*)d_in[0];
    const float* qkv_w   = (const float*)d_in[2];
    const float* qkv_b   = (const float*)d_in[3];
    const float* dense_w = (const float*)d_in[4];
    const float* dense_b = (const float*)d_in[5];
    const float* mlp_w1  = (const float*)d_in[6];
    const float* mlp_b1  = (const float*)d_in[7];
    const float* mlp_w2  = (const float*)d_in[8];
    const float* mlp_b2  = (const float*)d_in[9];
    const float* ln_in_g   = (const float*)d_in[10];
    const float* ln_in_b   = (const float*)d_in[11];
    const float* ln_post_g = (const float*)d_in[12];
    const float* ln_post_b = (const float*)d_in[13];
    const float* ln_s1_g   = (const float*)d_in[14];
    const float* ln_s1_b   = (const float*)d_in[15];
    const float* ln_s2_g   = (const float*)d_in[16];
    const float* ln_s2_b   = (const float*)d_in[17];

    cudaFuncSetAttribute(k_gemm<0,0>, cudaFuncAttributeMaxDynamicSharedMemorySize, GEMM_SMEM_DYN);
    cudaFuncSetAttribute(k_gemm<0,1>, cudaFuncAttributeMaxDynamicSharedMemorySize, GEMM_SMEM_DYN);
    cudaFuncSetAttribute(k_gemm<1,1>, cudaFuncAttributeMaxDynamicSharedMemorySize, GEMM_SMEM_DYN);
    cudaFuncSetAttribute(k_attn,      cudaFuncAttributeMaxDynamicSharedMemorySize, ATT_SMEM);

    float* h   = symaddrf(g_h);
    float* att = symaddrf(g_att);
    float* h2  = symaddrf(g_h2);
    float* m2  = symaddrf(g_m2);
    fp16* a0 = symaddrh(g_a0);   fp16* a1 = symaddrh(g_a1);
    fp16* q0 = symaddrh(g_qkv0); fp16* q1 = symaddrh(g_qkv1);
    fp16* c0 = symaddrh(g_c0);   fp16* c1 = symaddrh(g_c1);
    fp16* m1h = symaddrh(g_m1h); fp16* m1l = symaddrh(g_m1l);
    fp16* wq = symaddrh(g_wq);
    fp16* wd = symaddrh(g_wd);
    fp16* w1 = symaddrh(g_w1);
    fp16* w2 = symaddrh(g_w2);
    float* out = (float*)d_out;

    // ---- parallel branch: all weight converts on a side stream -------------
    cudaStream_t s1;
    cudaStreamCreateWithFlags(&s1, cudaStreamNonBlocking);
    cudaEvent_t evFork;
    cudaEventCreateWithFlags(&evFork, cudaEventDisableTiming);
    cudaEvent_t evW[LAYERS][4];
    for (int l = 0; l < LAYERS; l++)
        for (int k = 0; k < 4; k++)
            cudaEventCreateWithFlags(&evW[l][k], cudaEventDisableTiming);

    cudaEventRecord(evFork, 0);
    cudaStreamWaitEvent(s1, evFork, 0);
    for (int l = 0; l < LAYERS; l++) {
        {   size_t n = (size_t)H3 * HID; int n4 = (int)(n / 4);
            conv_fp32_fp16<<<(n4 + 255) / 256, 256, 0, s1>>>(
                qkv_w + (size_t)l * n, wq + (size_t)l * n, n4);
            cudaEventRecord(evW[l][0], s1); }
        {   size_t n = (size_t)HID * HID; int n4 = (int)(n / 4);
            conv_fp32_fp16<<<(n4 + 255) / 256, 256, 0, s1>>>(
                dense_w + (size_t)l * n, wd + (size_t)l * n, n4);
            cudaEventRecord(evW[l][1], s1); }
        {   size_t n = (size_t)H4 * HID; int n4 = (int)(n / 4);
            conv_fp32_fp16<<<(n4 + 255) / 256, 256, 0, s1>>>(
                mlp_w1 + (size_t)l * n, w1 + (size_t)l * n, n4);
            cudaEventRecord(evW[l][2], s1); }
        {   size_t n = (size_t)HID * H4; int n4 = (int)(n / 4);
            conv_fp32_fp16<<<(n4 + 255) / 256, 256, 0, s1>>>(
                mlp_w2 + (size_t)l * n, w2 + (size_t)l * n, n4);
            cudaEventRecord(evW[l][3], s1); }
    }

    // ---- main stream --------------------------------------------------------
    ln_split_kernel<<<ROWS, 256>>>(hidden, ln_in_g, ln_in_b, a0, a1);

    for (int l = 0; l < LAYERS; l++) {
        const float* hin = (l == 0) ? hidden : h;
        const float* l_qkv_b   = qkv_b   + (size_t)l * H3;
        const float* l_dense_b = dense_b + (size_t)l * HID;
        const float* l_b1 = mlp_b1 + (size_t)l * H4;
        const float* l_b2 = mlp_b2 + (size_t)l * HID;
        const fp16* l_wq = wq + (size_t)l * H3 * HID;
        const fp16* l_wd = wd + (size_t)l * HID * HID;
        const fp16* l_w1 = w1 + (size_t)l * H4 * HID;
        const fp16* l_w2 = w2 + (size_t)l * HID * H4;

        // qkv: Q columns full split-2; K/V columns hi-only (store AND compute)
        cudaStreamWaitEvent(0, evW[l][0], 0);
        k_gemm<0,1><<<dim3(H3/128, ROWS/128), 256, GEMM_SMEM_DYN>>>(
            a0, a1, l_wq, l_qkv_b, nullptr, q0, q1, ROWS, H3, HID, HID);

        // fused flash attention -> split ctx (heavy tiles first, all heads)
        k_attn<<<512, 256, ATT_SMEM>>>(q0, q1, c0, c1);

        // attn_out = ctx @ dense_w^T + b  (fp32)
        cudaStreamWaitEvent(0, evW[l][1], 0);
        k_gemm<0,0><<<dim3(HID/128, ROWS/128), 256, GEMM_SMEM_DYN>>>(
            c0, c1, l_wd, l_dense_b, att, nullptr, nullptr, ROWS, HID, HID, 0);

        // h2 = hin + LN_s1(att); a0/a1 = split(LN_post(h2))
        ln_res_split_kernel<1><<<ROWS, 256>>>(
            att, hin, ln_s1_g + l*HID, ln_s1_b + l*HID,
            ln_post_g + l*HID, ln_post_b + l*HID, h2, a0, a1);

        // m1 = gelu(y @ w1^T + b1) -> split (full split everywhere)
        cudaStreamWaitEvent(0, evW[l][2], 0);
        k_gemm<1,1><<<dim3(H4/128, ROWS/128), 256, GEMM_SMEM_DYN>>>(
            a0, a1, l_w1, l_b1, nullptr, m1h, m1l, ROWS, H4, HID, H4);

        // m2 = m1 @ w2^T + b2 (fp32)
        cudaStreamWaitEvent(0, evW[l][3], 0);
        k_gemm<0,0><<<dim3(HID/128, ROWS/128), 256, GEMM_SMEM_DYN>>>(
            m1h, m1l, l_w2, l_b2, m2, nullptr, nullptr, ROWS, HID, H4, 0);

        if (l + 1 < LAYERS) {
            ln_res_split_kernel<1><<<ROWS, 256>>>(
                m2, h2, ln_s2_g + l*HID, ln_s2_b + l*HID,
                ln_in_g + (l+1)*HID, ln_in_b + (l+1)*HID, h, a0, a1);
        } else {
            ln_res_split_kernel<0><<<ROWS, 256>>>(
                m2, h2, ln_s2_g + l*HID, ln_s2_b + l*HID,
                nullptr, nullptr, out, nullptr, nullptr);
        }
    }
}

// round 16
// speedup vs baseline: 1.0402x; 1.0402x over previous
#include <cuda_runtime.h>
#include <cuda_fp16.h>
#include <math.h>
#include <stdint.h>

// Problem constants
#define LAYERS 2
#define BATCH  4
#define SEQ    1024
#define HID    2048
#define NHEAD  16
#define HDIM   128
#define H3     (3*HID)
#define H4     (4*HID)
#define ROWS   (BATCH*SEQ)
#define NHEADS_TOT (BATCH*NHEAD)
#define EPSV   1e-5f

typedef __half fp16;

// ---------------------------------------------------------------------------
// Scratch (device globals)
// ---------------------------------------------------------------------------
__device__ float g_h   [(size_t)ROWS*HID];
__device__ float g_att [(size_t)ROWS*HID];
__device__ float g_h2  [(size_t)ROWS*HID];
__device__ float g_m2  [(size_t)ROWS*HID];
// fp16 split buffers
__device__ fp16 g_a0 [(size_t)ROWS*HID];
__device__ fp16 g_a1 [(size_t)ROWS*HID];
__device__ fp16 g_qkv0[(size_t)ROWS*H3];
__device__ fp16 g_qkv1[(size_t)ROWS*H3];
__device__ fp16 g_c0 [(size_t)ROWS*HID];
__device__ fp16 g_c1 [(size_t)ROWS*HID];
__device__ fp16 g_m1h[(size_t)ROWS*H4];
__device__ fp16 g_m1l[(size_t)ROWS*H4];
// per-layer fp16 weight buffers (converted on a parallel graph branch)
__device__ fp16 g_wq [(size_t)LAYERS*H3*HID];
__device__ fp16 g_wd [(size_t)LAYERS*HID*HID];
__device__ fp16 g_w1 [(size_t)LAYERS*H4*HID];
__device__ fp16 g_w2 [(size_t)LAYERS*HID*H4];

// ---------------------------------------------------------------------------
// Helpers
// ---------------------------------------------------------------------------
__device__ __forceinline__ uint32_t smem_u32(const void* p) {
    uint32_t a;
    asm("{ .reg .u64 t; cvta.to.shared.u64 t, %1; cvt.u32.u64 %0, t; }"
        : "=r"(a) : "l"(p));
    return a;
}
__device__ __forceinline__ void cp16(uint32_t dst, const void* src) {
    asm volatile("cp.async.cg.shared.global [%0], [%1], 16;"
                 :: "r"(dst), "l"(src) : "memory");
}
__device__ __forceinline__ void cp_commit() {
    asm volatile("cp.async.commit_group;" ::: "memory");
}
template<int N> __device__ __forceinline__ void cp_wait() {
    asm volatile("cp.async.wait_group %0;" :: "n"(N) : "memory");
}
__device__ __forceinline__ void mma16816(float* d, const uint32_t* a, const uint32_t* b) {
    asm volatile(
        "mma.sync.aligned.m16n8k16.row.col.f32.f16.f16.f32 "
        "{%0,%1,%2,%3}, {%4,%5,%6,%7}, {%8,%9}, {%0,%1,%2,%3};"
        : "+f"(d[0]), "+f"(d[1]), "+f"(d[2]), "+f"(d[3])
        : "r"(a[0]), "r"(a[1]), "r"(a[2]), "r"(a[3]), "r"(b[0]), "r"(b[1]));
}
__device__ __forceinline__ void ldsm4(uint32_t* r, uint32_t addr) {
    asm volatile("ldmatrix.sync.aligned.m8n8.x4.shared.b16 {%0,%1,%2,%3}, [%4];"
                 : "=r"(r[0]), "=r"(r[1]), "=r"(r[2]), "=r"(r[3]) : "r"(addr));
}
__device__ __forceinline__ void ldsm4t(uint32_t* r, uint32_t addr) {
    asm volatile("ldmatrix.sync.aligned.m8n8.x4.trans.shared.b16 {%0,%1,%2,%3}, [%4];"
                 : "=r"(r[0]), "=r"(r[1]), "=r"(r[2]), "=r"(r[3]) : "r"(addr));
}
__device__ __forceinline__ float gelu_f(float x) {
    float inner = 0.7978845608028654f * x * (1.0f + 0.044715f * x * x);
    return 0.5f * x * (1.0f + tanhf(inner));
}
__device__ __forceinline__ void st_split2(fp16* H, fp16* L, size_t off, float x, float y) {
    fp16 hx = __float2half_rn(x), hy = __float2half_rn(y);
    fp16 lx = __float2half_rn(x - __half2float(hx));
    fp16 ly = __float2half_rn(y - __half2float(hy));
    *reinterpret_cast<__half2*>(H + off) = __halves2half2(hx, hy);
    *reinterpret_cast<__half2*>(L + off) = __halves2half2(lx, ly);
}
__device__ __forceinline__ void st_hi2(fp16* H, size_t off, float x, float y) {
    *reinterpret_cast<__half2*>(H + off) =
        __halves2half2(__float2half_rn(x), __float2half_rn(y));
}
__device__ __forceinline__ void split_pack(float x, float y, uint32_t& hi, uint32_t& lo) {
    fp16 hx = __float2half_rn(x), hy = __float2half_rn(y);
    fp16 lx = __float2half_rn(x - __half2float(hx));
    fp16 ly = __float2half_rn(y - __half2float(hy));
    __half2 H = __halves2half2(hx, hy), L = __halves2half2(lx, ly);
    hi = *reinterpret_cast<uint32_t*>(&H);
    lo = *reinterpret_cast<uint32_t*>(&L);
}

// ---------------------------------------------------------------------------
// Block reduction (sum)
// ---------------------------------------------------------------------------
__device__ __forceinline__ float blockReduceSum256(float v) {
    __shared__ float sm[8];
    int lane = threadIdx.x & 31, w = threadIdx.x >> 5;
    #pragma unroll
    for (int o = 16; o > 0; o >>= 1) v += __shfl_xor_sync(0xffffffffu, v, o);
    if (lane == 0) sm[w] = v;
    __syncthreads();
    float r = sm[0];
    #pragma unroll
    for (int i = 1; i < 8; i++) r += sm[i];
    __syncthreads();
    return r;
}

// ---------------------------------------------------------------------------
// LayerNorm kernels
// ---------------------------------------------------------------------------
__global__ __launch_bounds__(256) void ln_split_kernel(
    const float* __restrict__ x, const float* __restrict__ gamma,
    const float* __restrict__ beta, fp16* __restrict__ hi, fp16* __restrict__ lo)
{
    const int row = blockIdx.x;
    const int tid = threadIdx.x;
    const float* xr = x + (size_t)row * HID;
    const int cb = tid * 8;

    float v[8];
    *reinterpret_cast<float4*>(v)     = *reinterpret_cast<const float4*>(xr + cb);
    *reinterpret_cast<float4*>(v + 4) = *reinterpret_cast<const float4*>(xr + cb + 4);
    float s = 0.f;
    #pragma unroll
    for (int i = 0; i < 8; i++) s += v[i];
    s = blockReduceSum256(s);
    const float mean = s * (1.0f / HID);

    float q = 0.f;
    #pragma unroll
    for (int i = 0; i < 8; i++) { float d = v[i] - mean; q += d * d; }
    q = blockReduceSum256(q);
    const float rstd = rsqrtf(q * (1.0f / HID) + EPSV);

    const size_t ob = (size_t)row * HID + cb;
    #pragma unroll
    for (int i = 0; i < 8; i += 2) {
        float o0 = (v[i]   - mean) * rstd * gamma[cb+i]   + beta[cb+i];
        float o1 = (v[i+1] - mean) * rstd * gamma[cb+i+1] + beta[cb+i+1];
        st_split2(hi, lo, ob + i, o0, o1);
    }
}

template<int DO_SPLIT>
__global__ __launch_bounds__(256) void ln_res_split_kernel(
    const float* __restrict__ x, const float* __restrict__ res,
    const float* __restrict__ g1, const float* __restrict__ b1,
    const float* __restrict__ g2, const float* __restrict__ b2,
    float* __restrict__ mid, fp16* __restrict__ hi, fp16* __restrict__ lo)
{
    const int row = blockIdx.x;
    const int tid = threadIdx.x;
    const int cb = tid * 8;
    const float* xr = x + (size_t)row * HID;
    const float* rr = res + (size_t)row * HID;

    float v[8];
    *reinterpret_cast<float4*>(v)     = *reinterpret_cast<const float4*>(xr + cb);
    *reinterpret_cast<float4*>(v + 4) = *reinterpret_cast<const float4*>(xr + cb + 4);
    float s = 0.f;
    #pragma unroll
    for (int i = 0; i < 8; i++) s += v[i];
    s = blockReduceSum256(s);
    const float mean = s * (1.0f / HID);

    float q = 0.f;
    #pragma unroll
    for (int i = 0; i < 8; i++) { float d = v[i] - mean; q += d * d; }
    q = blockReduceSum256(q);
    const float rstd = rsqrtf(q * (1.0f / HID) + EPSV);

    float m[8];
    float s2 = 0.f;
    #pragma unroll
    for (int i = 0; i < 8; i++) {
        int c = cb + i;
        m[i] = rr[c] + (v[i] - mean) * rstd * g1[c] + b1[c];
        s2 += m[i];
    }
    float* mr = mid + (size_t)row * HID;
    *reinterpret_cast<float4*>(mr + cb)     = *reinterpret_cast<float4*>(m);
    *reinterpret_cast<float4*>(mr + cb + 4) = *reinterpret_cast<float4*>(m + 4);

    if (DO_SPLIT) {
        s2 = blockReduceSum256(s2);
        const float mean2 = s2 * (1.0f / HID);
        float q2 = 0.f;
        #pragma unroll
        for (int i = 0; i < 8; i++) { float d = m[i] - mean2; q2 += d * d; }
        q2 = blockReduceSum256(q2);
        const float rstd2 = rsqrtf(q2 * (1.0f / HID) + EPSV);

        const size_t ob = (size_t)row * HID + cb;
        #pragma unroll
        for (int i = 0; i < 8; i += 2) {
            int c = cb + i;
            float o0 = (m[i]   - mean2) * rstd2 * g2[c]   + b2[c];
            float o1 = (m[i+1] - mean2) * rstd2 * g2[c+1] + b2[c+1];
            st_split2(hi, lo, ob + i, o0, o1);
        }
    }
}

// ---------------------------------------------------------------------------
// fp32 -> fp16 convert (weights: hi part only)
// ---------------------------------------------------------------------------
__global__ __launch_bounds__(256) void conv_fp32_fp16(
    const float* __restrict__ src, fp16* __restrict__ dst, int n4)
{
    int i = blockIdx.x * 256 + threadIdx.x;
    if (i >= n4) return;
    float4 v = reinterpret_cast<const float4*>(src)[i];
    __half2* dp = reinterpret_cast<__half2*>(dst);
    dp[2*i + 0] = __halves2half2(__float2half_rn(v.x), __float2half_rn(v.y));
    dp[2*i + 1] = __halves2half2(__float2half_rn(v.z), __float2half_rn(v.w));
}

// ---------------------------------------------------------------------------
// Dense 128x128 split-2 fp16 mma body (C = (A0+A1) @ B0^T).
// BK=64: 128B rows (8 chunks of 16B), swizzle chunk' = ch ^ (r&7).
// 2-stage, ONE barrier + ONE wait per BK=64 iteration (half of BK=32 cadence).
// Schedule: prologue loads stage0; iter it: wait<0> (stage it resident; its
// load was issued one full iteration earlier), barrier (frees other slot),
// issue stage it+1 into it, compute. 96KB smem -> 2 CTAs/SM.
// OUT_SPLIT cols >= lo_limit store hi only (K/V lo never read). Full split-2
// compute everywhere (R15 lesson: compute-skip is time-neutral, error-costly).
// ---------------------------------------------------------------------------
#define STAGE_BYTES 49152
#define GEMM_SMEM_DYN (2*STAGE_BYTES)

template<int GELU, int OUT_SPLIT>
__global__ __launch_bounds__(256, 2) void k_gemm(
    const fp16* __restrict__ A0g, const fp16* __restrict__ A1g,
    const fp16* __restrict__ B0g,
    const float* __restrict__ bias,
    float* __restrict__ Cf, fp16* __restrict__ Ch, fp16* __restrict__ Cl,
    int M, int N, int K, int lo_limit)
{
    extern __shared__ uint32_t smw[];
    const uint32_t smbase = smem_u32(smw);

    const int tid = threadIdx.x;
    const int wid = tid >> 5, lane = tid & 31;
    const int wm = wid & 3, wn = wid >> 2;
    const int g = lane >> 2, c = lane & 3;
    const int bm = blockIdx.y * 128;
    const int bn = blockIdx.x * 128;

    const char* pA0 = (const char*)(A0g + (size_t)bm * K);
    const char* pA1 = (const char*)(A1g + (size_t)bm * K);
    const char* pB0 = (const char*)(B0g + (size_t)bn * K);
    const size_t la = (size_t)K * 2;

    // stage: A0 @0, A1 @16384, B0 @32768; 3 tiles x 128 rows x 8 chunks = 3072 cp16
    auto load_stage = [&](int it, uint32_t sb) {
        #pragma unroll
        for (int i = 0; i < 12; i++) {
            int idx = tid + i * 256;          // 0..3071
            int t  = idx >> 10;               // tile 0..2
            int r  = (idx >> 3) & 127;        // row
            int ch = idx & 7;                 // 16B chunk within 128B row
            const char* base = (t == 0) ? pA0 : (t == 1) ? pA1 : pB0;
            cp16(sb + (uint32_t)(t * 16384 + r * 128 + ((ch ^ (r & 7)) << 4)),
                 base + (size_t)r * la + (size_t)it * 128 + ch * 16);
        }
    };

    const int ar   = (lane & 15);
    const int akh  = (lane >> 4) & 1;
    const int br   = (lane & 7) + ((lane & 16) ? 8 : 0);
    const int bkh  = (lane & 8) ? 1 : 0;

    float acc[2][8][4];
    #pragma unroll
    for (int i = 0; i < 2; i++)
        #pragma unroll
        for (int j = 0; j < 8; j++)
            #pragma unroll
            for (int k = 0; k < 4; k++) acc[i][j][k] = 0.f;

    const int nIter = K >> 6;

    load_stage(0, smbase);
    cp_commit();

    for (int it = 0; it < nIter; ++it) {
        cp_wait<0>();              // stage it resident (only group in flight)
        __syncthreads();           // all warps done reading the other slot

        if (it + 1 < nIter)
            load_stage(it + 1, smbase + (uint32_t)((it + 1) & 1) * STAGE_BYTES);
        cp_commit();

        const uint32_t sb = smbase + (uint32_t)(it & 1) * STAGE_BYTES;
        #pragma unroll
        for (int j = 0; j < 4; ++j) {         // 4 k16-steps per BK=64 stage
            uint32_t a0r[2][4], a1r[2][4];
            #pragma unroll
            for (int fm = 0; fm < 2; ++fm) {
                const int row = wm * 32 + fm * 16 + ar;
                uint32_t ao = sb + (uint32_t)(row * 128
                                  + (((2*j + akh) ^ (ar & 7)) << 4));
                ldsm4(a0r[fm], ao);
                ldsm4(a1r[fm], ao + 16384);
            }
            #pragma unroll
            for (int fn2 = 0; fn2 < 4; ++fn2) {
                uint32_t b0r[4];
                const int rowb = wn * 64 + fn2 * 16 + br;
                uint32_t bo = sb + 32768
                    + (uint32_t)(rowb * 128 + (((2*j + bkh) ^ (br & 7)) << 4));
                ldsm4(b0r, bo);
                #pragma unroll
                for (int fm = 0; fm < 2; ++fm) {
                    mma16816(acc[fm][2*fn2],   a0r[fm], b0r);
                    mma16816(acc[fm][2*fn2],   a1r[fm], b0r);
                    mma16816(acc[fm][2*fn2+1], a0r[fm], b0r + 2);
                    mma16816(acc[fm][2*fn2+1], a1r[fm], b0r + 2);
                }
            }
        }
    }

    // epilogue
    const bool want_lo = (bn < lo_limit);   // tile-uniform (128-aligned regions)
    #pragma unroll
    for (int fm = 0; fm < 2; ++fm) {
        const int r0 = bm + wm * 32 + fm * 16 + g;
        #pragma unroll
        for (int fn = 0; fn < 8; ++fn) {
            const int col = wn * 64 + fn * 8 + 2 * c;
            float bv0 = __ldg(&bias[bn + col]);
            float bv1 = __ldg(&bias[bn + col + 1]);
            float o0 = acc[fm][fn][0] + bv0;
            float o1 = acc[fm][fn][1] + bv1;
            float o2 = acc[fm][fn][2] + bv0;
            float o3 = acc[fm][fn][3] + bv1;
            if (GELU) { o0 = gelu_f(o0); o1 = gelu_f(o1); o2 = gelu_f(o2); o3 = gelu_f(o3); }
            const size_t off0 = (size_t)r0 * N + bn + col;
            const size_t off1 = (size_t)(r0 + 8) * N + bn + col;
            if (OUT_SPLIT) {
                if (want_lo) {
                    st_split2(Ch, Cl, off0, o0, o1);
                    st_split2(Ch, Cl, off1, o2, o3);
                } else {
                    st_hi2(Ch, off0, o0, o1);
                    st_hi2(Ch, off1, o2, o3);
                }
            } else {
                *reinterpret_cast<float2*>(Cf + off0) = make_float2(o0, o1);
                *reinterpret_cast<float2*>(Cf + off1) = make_float2(o2, o3);
            }
        }
    }
}

// ---------------------------------------------------------------------------
// Fused flash attention (R14 keeper): heavy-first 1D grid, split K/V commit
// groups (V load overlaps QK mma + log2-domain softmax).
// ---------------------------------------------------------------------------
#define ATT_SMEM (3*65536)

__global__ __launch_bounds__(256, 1) void k_attn(
    const fp16* __restrict__ q0, const fp16* __restrict__ q1,
    fp16* __restrict__ c0, fp16* __restrict__ c1)
{
    extern __shared__ char smc[];
    const uint32_t smb = smem_u32(smc);
    const int bid = blockIdx.x;
    const int st = 7 - (bid >> 6);
    const int hd = bid & 63;
    const int b = hd >> 4, n = hd & 15;
    const int tid = threadIdx.x, w = tid >> 5, lane = tid & 31;
    const int g = lane >> 2, c = lane & 3;

    const char* Qg0 = (const char*)(q0 + ((size_t)b*SEQ + (size_t)st*128)*H3 + (size_t)n*HDIM);
    const char* Qg1 = (const char*)(q1 + ((size_t)b*SEQ + (size_t)st*128)*H3 + (size_t)n*HDIM);
    const char* Kg  = (const char*)(q0 + (size_t)b*SEQ*H3 + HID     + (size_t)n*HDIM);
    const char* Vg  = (const char*)(q0 + (size_t)b*SEQ*H3 + 2*HID   + (size_t)n*HDIM);
    const size_t ldq = (size_t)H3 * 2;

    auto load_k = [&](int tt, int buf) {
        const uint32_t kb = smb + 65536u + (uint32_t)buf * 65536u;
        #pragma unroll
        for (int i = 0; i < 8; i++) {
            int idx = tid + i * 256;
            int rr = (idx >> 4) & 127, ch = idx & 15;
            cp16(kb + (uint32_t)(rr * 256 + ((ch ^ (rr & 7)) << 4)),
                 Kg + (size_t)(tt * 128 + rr) * ldq + (size_t)ch * 16);
        }
    };
    auto load_v = [&](int tt, int buf) {
        const uint32_t vb = smb + 65536u + (uint32_t)buf * 65536u + 32768u;
        #pragma unroll
        for (int i = 0; i < 8; i++) {
            int idx = tid + i * 256;
            int rr = (idx >> 4) & 127, ch = idx & 15;
            cp16(vb + (uint32_t)(rr * 256 + ((ch ^ (rr & 7)) << 4)),
                 Vg + (size_t)(tt * 128 + rr) * ldq + (size_t)ch * 16);
        }
    };

    // prologue: group A = Q(hi+lo) + K0; group B = V0
    #pragma unroll
    for (int i = 0; i < 16; i++) {
        int idx = tid + i * 256;
        int sp = idx >> 11, rr = (idx >> 4) & 127, ch = idx & 15;
        cp16(smb + (uint32_t)sp * 32768u
                 + (uint32_t)(rr * 256 + ((ch ^ (rr & 7)) << 4)),
             (sp ? Qg1 : Qg0) + (size_t)rr * ldq + (size_t)ch * 16);
    }
    load_k(0, 0);
    cp_commit();
    load_v(0, 0);
    cp_commit();

    const int ar  = lane & 15;
    const int akh = (lane >> 4) & 1;
    const int br  = (lane & 7) + ((lane & 16) ? 8 : 0);
    const int bkh = (lane & 8) ? 1 : 0;
    const int t0l = lane & 15;
    const int hi16 = (lane & 16) ? 1 : 0;

    float ctx[16][4];
    #pragma unroll
    for (int i = 0; i < 16; i++) { ctx[i][0]=ctx[i][1]=ctx[i][2]=ctx[i][3]=0.f; }
    float mr0 = -1e30f, mr1 = -1e30f, l0 = 0.f, l1 = 0.f;
    const float scale = 0.08838834764831845f * 1.4426950408889634f;  // /sqrt(128) * log2(e)
    const int nt = st + 1;

    for (int tt = 0; tt < nt; tt++) {
        const int buf = tt & 1;
        const bool has_next = (tt + 1 < nt);

        cp_wait<1>();      // retires K_tt
        __syncthreads();

        if (has_next) {
            load_k(tt + 1, buf ^ 1);
            cp_commit();
            load_v(tt + 1, buf ^ 1);
            cp_commit();
        }

        const uint32_t kb = smb + 65536u + (uint32_t)buf * 65536u;

        // ---- S = Q @ K^T (split-2 on Q) ----
        float s[16][4];
        #pragma unroll
        for (int i = 0; i < 16; i++) { s[i][0]=s[i][1]=s[i][2]=s[i][3]=0.f; }
        #pragma unroll
        for (int kf = 0; kf < 8; kf++) {
            uint32_t a0[4], a1[4];
            uint32_t qa = smb + (uint32_t)((w*16 + ar) * 256
                                           + (((kf*2 + akh) ^ (ar & 7)) << 4));
            ldsm4(a0, qa);
            ldsm4(a1, qa + 32768u);
            #pragma unroll
            for (int f2 = 0; f2 < 8; f2++) {
                uint32_t bb[4];
                ldsm4(bb, kb + (uint32_t)((f2*16 + br) * 256
                                          + (((kf*2 + bkh) ^ (br & 7)) << 4)));
                mma16816(s[2*f2],   a0, bb);   mma16816(s[2*f2],   a1, bb);
                mma16816(s[2*f2+1], a0, bb+2); mma16816(s[2*f2+1], a1, bb+2);
            }
        }

        // ---- scale (log2 domain) + causal mask (diagonal tile only) ----
        if (tt == st) {
            const int r0 = w*16 + g, r1 = r0 + 8;
            #pragma unroll
            for (int fn = 0; fn < 16; fn++) {
                int col0 = fn*8 + 2*c;
                s[fn][0] = (col0   > r0) ? -1e30f : s[fn][0]*scale;
                s[fn][1] = (col0+1 > r0) ? -1e30f : s[fn][1]*scale;
                s[fn][2] = (col0   > r1) ? -1e30f : s[fn][2]*scale;
                s[fn][3] = (col0+1 > r1) ? -1e30f : s[fn][3]*scale;
            }
        } else {
            #pragma unroll
            for (int fn = 0; fn < 16; fn++) {
                s[fn][0]*=scale; s[fn][1]*=scale; s[fn][2]*=scale; s[fn][3]*=scale;
            }
        }

        // ---- online softmax in log2 domain ----
        float m0 = -1e30f, m1 = -1e30f;
        #pragma unroll
        for (int fn = 0; fn < 16; fn++) {
            m0 = fmaxf(m0, fmaxf(s[fn][0], s[fn][1]));
            m1 = fmaxf(m1, fmaxf(s[fn][2], s[fn][3]));
        }
        m0 = fmaxf(m0, __shfl_xor_sync(0xffffffffu, m0, 1));
        m0 = fmaxf(m0, __shfl_xor_sync(0xffffffffu, m0, 2));
        m1 = fmaxf(m1, __shfl_xor_sync(0xffffffffu, m1, 1));
        m1 = fmaxf(m1, __shfl_xor_sync(0xffffffffu, m1, 2));
        const float mn0 = fmaxf(mr0, m0), mn1 = fmaxf(mr1, m1);
        const float cr0 = exp2f(mr0 - mn0), cr1 = exp2f(mr1 - mn1);
        mr0 = mn0; mr1 = mn1;
        l0 *= cr0; l1 *= cr1;
        #pragma unroll
        for (int fn = 0; fn < 16; fn++) {
            ctx[fn][0]*=cr0; ctx[fn][1]*=cr0; ctx[fn][2]*=cr1; ctx[fn][3]*=cr1;
        }
        float ps0 = 0.f, ps1 = 0.f;
        #pragma unroll
        for (int fn = 0; fn < 16; fn++) {
            float p0v = exp2f(s[fn][0]-mn0), p1v = exp2f(s[fn][1]-mn0);
            float p2v = exp2f(s[fn][2]-mn1), p3v = exp2f(s[fn][3]-mn1);
            s[fn][0]=p0v; s[fn][1]=p1v; s[fn][2]=p2v; s[fn][3]=p3v;
            ps0 += p0v + p1v; ps1 += p2v + p3v;
        }
        ps0 += __shfl_xor_sync(0xffffffffu, ps0, 1);
        ps0 += __shfl_xor_sync(0xffffffffu, ps0, 2);
        ps1 += __shfl_xor_sync(0xffffffffu, ps1, 1);
        ps1 += __shfl_xor_sync(0xffffffffu, ps1, 2);
        l0 += ps0; l1 += ps1;

        // ---- wait for V_tt only now ----
        if (has_next) cp_wait<2>();
        else          cp_wait<0>();
        __syncthreads();

        // ---- ctx += P @ V (split-2 on P; S C-frags are PV A-frags) ----
        const uint32_t vb = kb + 32768u;
        #pragma unroll
        for (int kf = 0; kf < 8; kf++) {
            uint32_t ahi[4], alo[4];
            split_pack(s[2*kf][0],   s[2*kf][1],   ahi[0], alo[0]);
            split_pack(s[2*kf][2],   s[2*kf][3],   ahi[1], alo[1]);
            split_pack(s[2*kf+1][0], s[2*kf+1][1], ahi[2], alo[2]);
            split_pack(s[2*kf+1][2], s[2*kf+1][3], ahi[3], alo[3]);
            const int t = kf*16 + t0l;
            #pragma unroll
            for (int f2 = 0; f2 < 8; f2++) {
                uint32_t bb[4];
                ldsm4t(bb, vb + (uint32_t)(t * 256
                                           + (((f2*2 + hi16) ^ (t & 7)) << 4)));
                mma16816(ctx[2*f2],   ahi, bb);   mma16816(ctx[2*f2],   alo, bb);
                mma16816(ctx[2*f2+1], ahi, bb+2); mma16816(ctx[2*f2+1], alo, bb+2);
            }
        }
    }

    // ---- epilogue: normalize and store split ctx ----
    const float inv0 = 1.0f / l0, inv1 = 1.0f / l1;
    const size_t base = ((size_t)b*SEQ + (size_t)st*128 + w*16 + g) * HID + (size_t)n*HDIM;
    #pragma unroll
    for (int fn = 0; fn < 16; fn++) {
        const int col = fn*8 + 2*c;
        st_split2(c0, c1, base + col,           ctx[fn][0]*inv0, ctx[fn][1]*inv0);
        st_split2(c0, c1, base + 8*HID + col,   ctx[fn][2]*inv1, ctx[fn][3]*inv1);
    }
}

// ---------------------------------------------------------------------------
// Host side
// ---------------------------------------------------------------------------
static float* symaddrf(const void* sym) {
    void* p = nullptr; cudaGetSymbolAddress(&p, sym); return (float*)p;
}
static fp16* symaddrh(const void* sym) {
    void* p = nullptr; cudaGetSymbolAddress(&p, sym); return (fp16*)p;
}

extern "C" void kernel_launch(void* const* d_in, const int* in_sizes, int n_in,
                              void* d_out, int out_size)
{
    const float* hidden  = (const float*)d_in[0];
    const float* qkv_w   = (const float*)d_in[2];
    const float* qkv_b   = (const float*)d_in[3];
    const float* dense_w = (const float*)d_in[4];
    const float* dense_b = (const float*)d_in[5];
    const float* mlp_w1  = (const float*)d_in[6];
    const float* mlp_b1  = (const float*)d_in[7];
    const float* mlp_w2  = (const float*)d_in[8];
    const float* mlp_b2  = (const float*)d_in[9];
    const float* ln_in_g   = (const float*)d_in[10];
    const float* ln_in_b   = (const float*)d_in[11];
    const float* ln_post_g = (const float*)d_in[12];
    const float* ln_post_b = (const float*)d_in[13];
    const float* ln_s1_g   = (const float*)d_in[14];
    const float* ln_s1_b   = (const float*)d_in[15];
    const float* ln_s2_g   = (const float*)d_in[16];
    const float* ln_s2_b   = (const float*)d_in[17];

    cudaFuncSetAttribute(k_gemm<0,0>, cudaFuncAttributeMaxDynamicSharedMemorySize, GEMM_SMEM_DYN);
    cudaFuncSetAttribute(k_gemm<0,1>, cudaFuncAttributeMaxDynamicSharedMemorySize, GEMM_SMEM_DYN);
    cudaFuncSetAttribute(k_gemm<1,1>, cudaFuncAttributeMaxDynamicSharedMemorySize, GEMM_SMEM_DYN);
    cudaFuncSetAttribute(k_attn,      cudaFuncAttributeMaxDynamicSharedMemorySize, ATT_SMEM);

    float* h   = symaddrf(g_h);
    float* att = symaddrf(g_att);
    float* h2  = symaddrf(g_h2);
    float* m2  = symaddrf(g_m2);
    fp16* a0 = symaddrh(g_a0);   fp16* a1 = symaddrh(g_a1);
    fp16* q0 = symaddrh(g_qkv0); fp16* q1 = symaddrh(g_qkv1);
    fp16* c0 = symaddrh(g_c0);   fp16* c1 = symaddrh(g_c1);
    fp16* m1h = symaddrh(g_m1h); fp16* m1l = symaddrh(g_m1l);
    fp16* wq = symaddrh(g_wq);
    fp16* wd = symaddrh(g_wd);
    fp16* w1 = symaddrh(g_w1);
    fp16* w2 = symaddrh(g_w2);
    float* out = (float*)d_out;

    // ---- parallel branch: all weight converts on a side stream -------------
    cudaStream_t s1;
    cudaStreamCreateWithFlags(&s1, cudaStreamNonBlocking);
    cudaEvent_t evFork;
    cudaEventCreateWithFlags(&evFork, cudaEventDisableTiming);
    cudaEvent_t evW[LAYERS][4];
    for (int l = 0; l < LAYERS; l++)
        for (int k = 0; k < 4; k++)
            cudaEventCreateWithFlags(&evW[l][k], cudaEventDisableTiming);

    cudaEventRecord(evFork, 0);
    cudaStreamWaitEvent(s1, evFork, 0);
    for (int l = 0; l < LAYERS; l++) {
        {   size_t n = (size_t)H3 * HID; int n4 = (int)(n / 4);
            conv_fp32_fp16<<<(n4 + 255) / 256, 256, 0, s1>>>(
                qkv_w + (size_t)l * n, wq + (size_t)l * n, n4);
            cudaEventRecord(evW[l][0], s1); }
        {   size_t n = (size_t)HID * HID; int n4 = (int)(n / 4);
            conv_fp32_fp16<<<(n4 + 255) / 256, 256, 0, s1>>>(
                dense_w + (size_t)l * n, wd + (size_t)l * n, n4);
            cudaEventRecord(evW[l][1], s1); }
        {   size_t n = (size_t)H4 * HID; int n4 = (int)(n / 4);
            conv_fp32_fp16<<<(n4 + 255) / 256, 256, 0, s1>>>(
                mlp_w1 + (size_t)l * n, w1 + (size_t)l * n, n4);
            cudaEventRecord(evW[l][2], s1); }
        {   size_t n = (size_t)HID * H4; int n4 = (int)(n / 4);
            conv_fp32_fp16<<<(n4 + 255) / 256, 256, 0, s1>>>(
                mlp_w2 + (size_t)l * n, w2 + (size_t)l * n, n4);
            cudaEventRecord(evW[l][3], s1); }
    }

    // ---- main stream --------------------------------------------------------
    ln_split_kernel<<<ROWS, 256>>>(hidden, ln_in_g, ln_in_b, a0, a1);

    for (int l = 0; l < LAYERS; l++) {
        const float* hin = (l == 0) ? hidden : h;
        const float* l_qkv_b   = qkv_b   + (size_t)l * H3;
        const float* l_dense_b = dense_b + (size_t)l * HID;
        const float* l_b1 = mlp_b1 + (size_t)l * H4;
        const float* l_b2 = mlp_b2 + (size_t)l * HID;
        const fp16* l_wq = wq + (size_t)l * H3 * HID;
        const fp16* l_wd = wd + (size_t)l * HID * HID;
        const fp16* l_w1 = w1 + (size_t)l * H4 * HID;
        const fp16* l_w2 = w2 + (size_t)l * HID * H4;

        // qkv: full split-2 compute; K/V columns hi-only store
        cudaStreamWaitEvent(0, evW[l][0], 0);
        k_gemm<0,1><<<dim3(H3/128, ROWS/128), 256, GEMM_SMEM_DYN>>>(
            a0, a1, l_wq, l_qkv_b, nullptr, q0, q1, ROWS, H3, HID, HID);

        // fused flash attention -> split ctx (heavy tiles first, all heads)
        k_attn<<<512, 256, ATT_SMEM>>>(q0, q1, c0, c1);

        // attn_out = ctx @ dense_w^T + b  (fp32)
        cudaStreamWaitEvent(0, evW[l][1], 0);
        k_gemm<0,0><<<dim3(HID/128, ROWS/128), 256, GEMM_SMEM_DYN>>>(
            c0, c1, l_wd, l_dense_b, att, nullptr, nullptr, ROWS, HID, HID, 0);

        // h2 = hin + LN_s1(att); a0/a1 = split(LN_post(h2))
        ln_res_split_kernel<1><<<ROWS, 256>>>(
            att, hin, ln_s1_g + l*HID, ln_s1_b + l*HID,
            ln_post_g + l*HID, ln_post_b + l*HID, h2, a0, a1);

        // m1 = gelu(y @ w1^T + b1) -> split (full split everywhere)
        cudaStreamWaitEvent(0, evW[l][2], 0);
        k_gemm<1,1><<<dim3(H4/128, ROWS/128), 256, GEMM_SMEM_DYN>>>(
            a0, a1, l_w1, l_b1, nullptr, m1h, m1l, ROWS, H4, HID, H4);

        // m2 = m1 @ w2^T + b2 (fp32)
        cudaStreamWaitEvent(0, evW[l][3], 0);
        k_gemm<0,0><<<dim3(HID/128, ROWS/128), 256, GEMM_SMEM_DYN>>>(
            m1h, m1l, l_w2, l_b2, m2, nullptr, nullptr, ROWS, HID, H4, 0);

        if (l + 1 < LAYERS) {
            ln_res_split_kernel<1><<<ROWS, 256>>>(
                m2, h2, ln_s2_g + l*HID, ln_s2_b + l*HID,
                ln_in_g + (l+1)*HID, ln_in_b + (l+1)*HID, h, a0, a1);
        } else {
            ln_res_split_kernel<0><<<ROWS, 256>>>(
                m2, h2, ln_s2_g + l*HID, ln_s2_b + l*HID,
                nullptr, nullptr, out, nullptr, nullptr);
        }
    }
}

// round 17
// speedup vs baseline: 1.0419x; 1.0017x over previous
#include <cuda_runtime.h>
#include <cuda_fp16.h>
#include <math.h>
#include <stdint.h>

// Problem constants
#define LAYERS 2
#define BATCH  4
#define SEQ    1024
#define HID    2048
#define NHEAD  16
#define HDIM   128
#define H3     (3*HID)
#define H4     (4*HID)
#define ROWS   (BATCH*SEQ)
#define NHEADS_TOT (BATCH*NHEAD)
#define EPSV   1e-5f

typedef __half fp16;

// ---------------------------------------------------------------------------
// Scratch (device globals)
// ---------------------------------------------------------------------------
__device__ float g_h   [(size_t)ROWS*HID];
__device__ float g_att [(size_t)ROWS*HID];
__device__ float g_h2  [(size_t)ROWS*HID];
__device__ float g_m2  [(size_t)ROWS*HID];
// fp16 split buffers
__device__ fp16 g_a0 [(size_t)ROWS*HID];
__device__ fp16 g_a1 [(size_t)ROWS*HID];
__device__ fp16 g_qkv0[(size_t)ROWS*H3];
__device__ fp16 g_qkv1[(size_t)ROWS*H3];
__device__ fp16 g_c0 [(size_t)ROWS*HID];
__device__ fp16 g_c1 [(size_t)ROWS*HID];
__device__ fp16 g_m1h[(size_t)ROWS*H4];
__device__ fp16 g_m1l[(size_t)ROWS*H4];
// per-layer fp16 weight buffers (converted on a parallel graph branch)
__device__ fp16 g_wq [(size_t)LAYERS*H3*HID];
__device__ fp16 g_wd [(size_t)LAYERS*HID*HID];
__device__ fp16 g_w1 [(size_t)LAYERS*H4*HID];
__device__ fp16 g_w2 [(size_t)LAYERS*HID*H4];

// ---------------------------------------------------------------------------
// Helpers
// ---------------------------------------------------------------------------
__device__ __forceinline__ uint32_t smem_u32(const void* p) {
    uint32_t a;
    asm("{ .reg .u64 t; cvta.to.shared.u64 t, %1; cvt.u32.u64 %0, t; }"
        : "=r"(a) : "l"(p));
    return a;
}
__device__ __forceinline__ void cp16(uint32_t dst, const void* src) {
    asm volatile("cp.async.cg.shared.global [%0], [%1], 16;"
                 :: "r"(dst), "l"(src) : "memory");
}
__device__ __forceinline__ void cp_commit() {
    asm volatile("cp.async.commit_group;" ::: "memory");
}
template<int N> __device__ __forceinline__ void cp_wait() {
    asm volatile("cp.async.wait_group %0;" :: "n"(N) : "memory");
}
__device__ __forceinline__ void mma16816(float* d, const uint32_t* a, const uint32_t* b) {
    asm volatile(
        "mma.sync.aligned.m16n8k16.row.col.f32.f16.f16.f32 "
        "{%0,%1,%2,%3}, {%4,%5,%6,%7}, {%8,%9}, {%0,%1,%2,%3};"
        : "+f"(d[0]), "+f"(d[1]), "+f"(d[2]), "+f"(d[3])
        : "r"(a[0]), "r"(a[1]), "r"(a[2]), "r"(a[3]), "r"(b[0]), "r"(b[1]));
}
__device__ __forceinline__ void ldsm4(uint32_t* r, uint32_t addr) {
    asm volatile("ldmatrix.sync.aligned.m8n8.x4.shared.b16 {%0,%1,%2,%3}, [%4];"
                 : "=r"(r[0]), "=r"(r[1]), "=r"(r[2]), "=r"(r[3]) : "r"(addr));
}
__device__ __forceinline__ void ldsm4t(uint32_t* r, uint32_t addr) {
    asm volatile("ldmatrix.sync.aligned.m8n8.x4.trans.shared.b16 {%0,%1,%2,%3}, [%4];"
                 : "=r"(r[0]), "=r"(r[1]), "=r"(r[2]), "=r"(r[3]) : "r"(addr));
}
__device__ __forceinline__ float gelu_f(float x) {
    float inner = 0.7978845608028654f * x * (1.0f + 0.044715f * x * x);
    return 0.5f * x * (1.0f + tanhf(inner));
}
__device__ __forceinline__ void st_split2(fp16* H, fp16* L, size_t off, float x, float y) {
    fp16 hx = __float2half_rn(x), hy = __float2half_rn(y);
    fp16 lx = __float2half_rn(x - __half2float(hx));
    fp16 ly = __float2half_rn(y - __half2float(hy));
    *reinterpret_cast<__half2*>(H + off) = __halves2half2(hx, hy);
    *reinterpret_cast<__half2*>(L + off) = __halves2half2(lx, ly);
}
__device__ __forceinline__ void st_hi2(fp16* H, size_t off, float x, float y) {
    *reinterpret_cast<__half2*>(H + off) =
        __halves2half2(__float2half_rn(x), __float2half_rn(y));
}
__device__ __forceinline__ void split_pack(float x, float y, uint32_t& hi, uint32_t& lo) {
    fp16 hx = __float2half_rn(x), hy = __float2half_rn(y);
    fp16 lx = __float2half_rn(x - __half2float(hx));
    fp16 ly = __float2half_rn(y - __half2float(hy));
    __half2 H = __halves2half2(hx, hy), L = __halves2half2(lx, ly);
    hi = *reinterpret_cast<uint32_t*>(&H);
    lo = *reinterpret_cast<uint32_t*>(&L);
}
__device__ __forceinline__ uint32_t pack2(float x, float y) {
    __half2 H = __halves2half2(__float2half_rn(x), __float2half_rn(y));
    return *reinterpret_cast<uint32_t*>(&H);
}

// ---------------------------------------------------------------------------
// Block reduction (sum)
// ---------------------------------------------------------------------------
__device__ __forceinline__ float blockReduceSum256(float v) {
    __shared__ float sm[8];
    int lane = threadIdx.x & 31, w = threadIdx.x >> 5;
    #pragma unroll
    for (int o = 16; o > 0; o >>= 1) v += __shfl_xor_sync(0xffffffffu, v, o);
    if (lane == 0) sm[w] = v;
    __syncthreads();
    float r = sm[0];
    #pragma unroll
    for (int i = 1; i < 8; i++) r += sm[i];
    __syncthreads();
    return r;
}

// ---------------------------------------------------------------------------
// LayerNorm kernels
// ---------------------------------------------------------------------------
__global__ __launch_bounds__(256) void ln_split_kernel(
    const float* __restrict__ x, const float* __restrict__ gamma,
    const float* __restrict__ beta, fp16* __restrict__ hi, fp16* __restrict__ lo)
{
    const int row = blockIdx.x;
    const int tid = threadIdx.x;
    const float* xr = x + (size_t)row * HID;
    const int cb = tid * 8;

    float v[8];
    *reinterpret_cast<float4*>(v)     = *reinterpret_cast<const float4*>(xr + cb);
    *reinterpret_cast<float4*>(v + 4) = *reinterpret_cast<const float4*>(xr + cb + 4);
    float s = 0.f;
    #pragma unroll
    for (int i = 0; i < 8; i++) s += v[i];
    s = blockReduceSum256(s);
    const float mean = s * (1.0f / HID);

    float q = 0.f;
    #pragma unroll
    for (int i = 0; i < 8; i++) { float d = v[i] - mean; q += d * d; }
    q = blockReduceSum256(q);
    const float rstd = rsqrtf(q * (1.0f / HID) + EPSV);

    const size_t ob = (size_t)row * HID + cb;
    #pragma unroll
    for (int i = 0; i < 8; i += 2) {
        float o0 = (v[i]   - mean) * rstd * gamma[cb+i]   + beta[cb+i];
        float o1 = (v[i+1] - mean) * rstd * gamma[cb+i+1] + beta[cb+i+1];
        st_split2(hi, lo, ob + i, o0, o1);
    }
}

template<int DO_SPLIT>
__global__ __launch_bounds__(256) void ln_res_split_kernel(
    const float* __restrict__ x, const float* __restrict__ res,
    const float* __restrict__ g1, const float* __restrict__ b1,
    const float* __restrict__ g2, const float* __restrict__ b2,
    float* __restrict__ mid, fp16* __restrict__ hi, fp16* __restrict__ lo)
{
    const int row = blockIdx.x;
    const int tid = threadIdx.x;
    const int cb = tid * 8;
    const float* xr = x + (size_t)row * HID;
    const float* rr = res + (size_t)row * HID;

    float v[8];
    *reinterpret_cast<float4*>(v)     = *reinterpret_cast<const float4*>(xr + cb);
    *reinterpret_cast<float4*>(v + 4) = *reinterpret_cast<const float4*>(xr + cb + 4);
    float s = 0.f;
    #pragma unroll
    for (int i = 0; i < 8; i++) s += v[i];
    s = blockReduceSum256(s);
    const float mean = s * (1.0f / HID);

    float q = 0.f;
    #pragma unroll
    for (int i = 0; i < 8; i++) { float d = v[i] - mean; q += d * d; }
    q = blockReduceSum256(q);
    const float rstd = rsqrtf(q * (1.0f / HID) + EPSV);

    float m[8];
    float s2 = 0.f;
    #pragma unroll
    for (int i = 0; i < 8; i++) {
        int c = cb + i;
        m[i] = rr[c] + (v[i] - mean) * rstd * g1[c] + b1[c];
        s2 += m[i];
    }
    float* mr = mid + (size_t)row * HID;
    *reinterpret_cast<float4*>(mr + cb)     = *reinterpret_cast<float4*>(m);
    *reinterpret_cast<float4*>(mr + cb + 4) = *reinterpret_cast<float4*>(m + 4);

    if (DO_SPLIT) {
        s2 = blockReduceSum256(s2);
        const float mean2 = s2 * (1.0f / HID);
        float q2 = 0.f;
        #pragma unroll
        for (int i = 0; i < 8; i++) { float d = m[i] - mean2; q2 += d * d; }
        q2 = blockReduceSum256(q2);
        const float rstd2 = rsqrtf(q2 * (1.0f / HID) + EPSV);

        const size_t ob = (size_t)row * HID + cb;
        #pragma unroll
        for (int i = 0; i < 8; i += 2) {
            int c = cb + i;
            float o0 = (m[i]   - mean2) * rstd2 * g2[c]   + b2[c];
            float o1 = (m[i+1] - mean2) * rstd2 * g2[c+1] + b2[c+1];
            st_split2(hi, lo, ob + i, o0, o1);
        }
    }
}

// ---------------------------------------------------------------------------
// fp32 -> fp16 convert (weights: hi only). Streaming cache hints: each weight
// is read once and consumed later by cp.async; keep it out of L2's way while
// main-stream GEMMs run concurrently.
// ---------------------------------------------------------------------------
__global__ __launch_bounds__(256) void conv_fp32_fp16(
    const float* __restrict__ src, fp16* __restrict__ dst, int n4)
{
    int i = blockIdx.x * 256 + threadIdx.x;
    if (i >= n4) return;
    float4 v = __ldcs(reinterpret_cast<const float4*>(src) + i);
    uint2 o;
    o.x = pack2(v.x, v.y);
    o.y = pack2(v.z, v.w);
    __stcs(reinterpret_cast<uint2*>(dst) + i, o);
}

// ---------------------------------------------------------------------------
// Dense 128x128 split-2 fp16 mma body (C = (A0+A1) @ B0^T).
// BK=64: 128B rows (8 chunks of 16B), swizzle chunk' = ch ^ (r&7).
// 2-stage, ONE barrier + ONE wait per BK=64 iteration. 96KB -> 2 CTAs/SM.
// OUT_SPLIT cols >= lo_limit store hi only (K/V lo never read). Full split-2
// compute everywhere.
// ---------------------------------------------------------------------------
#define STAGE_BYTES 49152
#define GEMM_SMEM_DYN (2*STAGE_BYTES)

template<int GELU, int OUT_SPLIT>
__global__ __launch_bounds__(256, 2) void k_gemm(
    const fp16* __restrict__ A0g, const fp16* __restrict__ A1g,
    const fp16* __restrict__ B0g,
    const float* __restrict__ bias,
    float* __restrict__ Cf, fp16* __restrict__ Ch, fp16* __restrict__ Cl,
    int M, int N, int K, int lo_limit)
{
    extern __shared__ uint32_t smw[];
    const uint32_t smbase = smem_u32(smw);

    const int tid = threadIdx.x;
    const int wid = tid >> 5, lane = tid & 31;
    const int wm = wid & 3, wn = wid >> 2;
    const int g = lane >> 2, c = lane & 3;
    const int bm = blockIdx.y * 128;
    const int bn = blockIdx.x * 128;

    const char* pA0 = (const char*)(A0g + (size_t)bm * K);
    const char* pA1 = (const char*)(A1g + (size_t)bm * K);
    const char* pB0 = (const char*)(B0g + (size_t)bn * K);
    const size_t la = (size_t)K * 2;

    // stage: A0 @0, A1 @16384, B0 @32768; 3 tiles x 128 rows x 8 chunks = 3072 cp16
    auto load_stage = [&](int it, uint32_t sb) {
        #pragma unroll
        for (int i = 0; i < 12; i++) {
            int idx = tid + i * 256;          // 0..3071
            int t  = idx >> 10;               // tile 0..2
            int r  = (idx >> 3) & 127;        // row
            int ch = idx & 7;                 // 16B chunk within 128B row
            const char* base = (t == 0) ? pA0 : (t == 1) ? pA1 : pB0;
            cp16(sb + (uint32_t)(t * 16384 + r * 128 + ((ch ^ (r & 7)) << 4)),
                 base + (size_t)r * la + (size_t)it * 128 + ch * 16);
        }
    };

    const int ar   = (lane & 15);
    const int akh  = (lane >> 4) & 1;
    const int br   = (lane & 7) + ((lane & 16) ? 8 : 0);
    const int bkh  = (lane & 8) ? 1 : 0;

    float acc[2][8][4];
    #pragma unroll
    for (int i = 0; i < 2; i++)
        #pragma unroll
        for (int j = 0; j < 8; j++)
            #pragma unroll
            for (int k = 0; k < 4; k++) acc[i][j][k] = 0.f;

    const int nIter = K >> 6;

    load_stage(0, smbase);
    cp_commit();

    for (int it = 0; it < nIter; ++it) {
        cp_wait<0>();              // stage it resident (only group in flight)
        __syncthreads();           // all warps done reading the other slot

        if (it + 1 < nIter)
            load_stage(it + 1, smbase + (uint32_t)((it + 1) & 1) * STAGE_BYTES);
        cp_commit();

        const uint32_t sb = smbase + (uint32_t)(it & 1) * STAGE_BYTES;
        #pragma unroll
        for (int j = 0; j < 4; ++j) {         // 4 k16-steps per BK=64 stage
            uint32_t a0r[2][4], a1r[2][4];
            #pragma unroll
            for (int fm = 0; fm < 2; ++fm) {
                const int row = wm * 32 + fm * 16 + ar;
                uint32_t ao = sb + (uint32_t)(row * 128
                                  + (((2*j + akh) ^ (ar & 7)) << 4));
                ldsm4(a0r[fm], ao);
                ldsm4(a1r[fm], ao + 16384);
            }
            #pragma unroll
            for (int fn2 = 0; fn2 < 4; ++fn2) {
                uint32_t b0r[4];
                const int rowb = wn * 64 + fn2 * 16 + br;
                uint32_t bo = sb + 32768
                    + (uint32_t)(rowb * 128 + (((2*j + bkh) ^ (br & 7)) << 4));
                ldsm4(b0r, bo);
                #pragma unroll
                for (int fm = 0; fm < 2; ++fm) {
                    mma16816(acc[fm][2*fn2],   a0r[fm], b0r);
                    mma16816(acc[fm][2*fn2],   a1r[fm], b0r);
                    mma16816(acc[fm][2*fn2+1], a0r[fm], b0r + 2);
                    mma16816(acc[fm][2*fn2+1], a1r[fm], b0r + 2);
                }
            }
        }
    }

    // epilogue
    const bool want_lo = (bn < lo_limit);   // tile-uniform (128-aligned regions)
    #pragma unroll
    for (int fm = 0; fm < 2; ++fm) {
        const int r0 = bm + wm * 32 + fm * 16 + g;
        #pragma unroll
        for (int fn = 0; fn < 8; ++fn) {
            const int col = wn * 64 + fn * 8 + 2 * c;
            float bv0 = __ldg(&bias[bn + col]);
            float bv1 = __ldg(&bias[bn + col + 1]);
            float o0 = acc[fm][fn][0] + bv0;
            float o1 = acc[fm][fn][1] + bv1;
            float o2 = acc[fm][fn][2] + bv0;
            float o3 = acc[fm][fn][3] + bv1;
            if (GELU) { o0 = gelu_f(o0); o1 = gelu_f(o1); o2 = gelu_f(o2); o3 = gelu_f(o3); }
            const size_t off0 = (size_t)r0 * N + bn + col;
            const size_t off1 = (size_t)(r0 + 8) * N + bn + col;
            if (OUT_SPLIT) {
                if (want_lo) {
                    st_split2(Ch, Cl, off0, o0, o1);
                    st_split2(Ch, Cl, off1, o2, o3);
                } else {
                    st_hi2(Ch, off0, o0, o1);
                    st_hi2(Ch, off1, o2, o3);
                }
            } else {
                *reinterpret_cast<float2*>(Cf + off0) = make_float2(o0, o1);
                *reinterpret_cast<float2*>(Cf + off1) = make_float2(o2, o3);
            }
        }
    }
}

// ---------------------------------------------------------------------------
// Fused flash attention: heavy-first 1D grid, split K/V commit groups
// (V load overlaps QK mma + log2-domain softmax). Q fragments are kv-tile
// invariant: preloaded into registers at tt=0 (Q resident after first wait).
// ---------------------------------------------------------------------------
#define ATT_SMEM (3*65536)

__global__ __launch_bounds__(256, 1) void k_attn(
    const fp16* __restrict__ q0, const fp16* __restrict__ q1,
    fp16* __restrict__ c0, fp16* __restrict__ c1)
{
    extern __shared__ char smc[];
    const uint32_t smb = smem_u32(smc);
    const int bid = blockIdx.x;
    const int st = 7 - (bid >> 6);
    const int hd = bid & 63;
    const int b = hd >> 4, n = hd & 15;
    const int tid = threadIdx.x, w = tid >> 5, lane = tid & 31;
    const int g = lane >> 2, c = lane & 3;

    const char* Qg0 = (const char*)(q0 + ((size_t)b*SEQ + (size_t)st*128)*H3 + (size_t)n*HDIM);
    const char* Qg1 = (const char*)(q1 + ((size_t)b*SEQ + (size_t)st*128)*H3 + (size_t)n*HDIM);
    const char* Kg  = (const char*)(q0 + (size_t)b*SEQ*H3 + HID     + (size_t)n*HDIM);
    const char* Vg  = (const char*)(q0 + (size_t)b*SEQ*H3 + 2*HID   + (size_t)n*HDIM);
    const size_t ldq = (size_t)H3 * 2;

    auto load_k = [&](int tt, int buf) {
        const uint32_t kb = smb + 65536u + (uint32_t)buf * 65536u;
        #pragma unroll
        for (int i = 0; i < 8; i++) {
            int idx = tid + i * 256;
            int rr = (idx >> 4) & 127, ch = idx & 15;
            cp16(kb + (uint32_t)(rr * 256 + ((ch ^ (rr & 7)) << 4)),
                 Kg + (size_t)(tt * 128 + rr) * ldq + (size_t)ch * 16);
        }
    };
    auto load_v = [&](int tt, int buf) {
        const uint32_t vb = smb + 65536u + (uint32_t)buf * 65536u + 32768u;
        #pragma unroll
        for (int i = 0; i < 8; i++) {
            int idx = tid + i * 256;
            int rr = (idx >> 4) & 127, ch = idx & 15;
            cp16(vb + (uint32_t)(rr * 256 + ((ch ^ (rr & 7)) << 4)),
                 Vg + (size_t)(tt * 128 + rr) * ldq + (size_t)ch * 16);
        }
    };

    // prologue: group A = Q(hi+lo) + K0; group B = V0
    #pragma unroll
    for (int i = 0; i < 16; i++) {
        int idx = tid + i * 256;
        int sp = idx >> 11, rr = (idx >> 4) & 127, ch = idx & 15;
        cp16(smb + (uint32_t)sp * 32768u
                 + (uint32_t)(rr * 256 + ((ch ^ (rr & 7)) << 4)),
             (sp ? Qg1 : Qg0) + (size_t)rr * ldq + (size_t)ch * 16);
    }
    load_k(0, 0);
    cp_commit();
    load_v(0, 0);
    cp_commit();

    const int ar  = lane & 15;
    const int akh = (lane >> 4) & 1;
    const int br  = (lane & 7) + ((lane & 16) ? 8 : 0);
    const int bkh = (lane & 8) ? 1 : 0;
    const int t0l = lane & 15;
    const int hi16 = (lane & 16) ? 1 : 0;

    uint32_t qa0[8][4], qa1[8][4];   // Q fragments, tile-invariant
    float ctx[16][4];
    #pragma unroll
    for (int i = 0; i < 16; i++) { ctx[i][0]=ctx[i][1]=ctx[i][2]=ctx[i][3]=0.f; }
    float mr0 = -1e30f, mr1 = -1e30f, l0 = 0.f, l1 = 0.f;
    const float scale = 0.08838834764831845f * 1.4426950408889634f;  // /sqrt(128) * log2(e)
    const int nt = st + 1;

    for (int tt = 0; tt < nt; tt++) {
        const int buf = tt & 1;
        const bool has_next = (tt + 1 < nt);

        cp_wait<1>();      // retires K_tt (and Q at tt=0)
        __syncthreads();

        if (tt == 0) {
            // one-time Q fragment preload (hi + lo)
            #pragma unroll
            for (int kf = 0; kf < 8; kf++) {
                uint32_t qa = smb + (uint32_t)((w*16 + ar) * 256
                                               + (((kf*2 + akh) ^ (ar & 7)) << 4));
                ldsm4(qa0[kf], qa);
                ldsm4(qa1[kf], qa + 32768u);
            }
        }

        if (has_next) {
            load_k(tt + 1, buf ^ 1);
            cp_commit();
            load_v(tt + 1, buf ^ 1);
            cp_commit();
        }

        const uint32_t kb = smb + 65536u + (uint32_t)buf * 65536u;

        // ---- S = Q @ K^T (split-2 on Q; Q frags in registers) ----
        float s[16][4];
        #pragma unroll
        for (int i = 0; i < 16; i++) { s[i][0]=s[i][1]=s[i][2]=s[i][3]=0.f; }
        #pragma unroll
        for (int kf = 0; kf < 8; kf++) {
            #pragma unroll
            for (int f2 = 0; f2 < 8; f2++) {
                uint32_t bb[4];
                ldsm4(bb, kb + (uint32_t)((f2*16 + br) * 256
                                          + (((kf*2 + bkh) ^ (br & 7)) << 4)));
                mma16816(s[2*f2],   qa0[kf], bb);   mma16816(s[2*f2],   qa1[kf], bb);
                mma16816(s[2*f2+1], qa0[kf], bb+2); mma16816(s[2*f2+1], qa1[kf], bb+2);
            }
        }

        // ---- scale (log2 domain) + causal mask (diagonal tile only) ----
        if (tt == st) {
            const int r0 = w*16 + g, r1 = r0 + 8;
            #pragma unroll
            for (int fn = 0; fn < 16; fn++) {
                int col0 = fn*8 + 2*c;
                s[fn][0] = (col0   > r0) ? -1e30f : s[fn][0]*scale;
                s[fn][1] = (col0+1 > r0) ? -1e30f : s[fn][1]*scale;
                s[fn][2] = (col0   > r1) ? -1e30f : s[fn][2]*scale;
                s[fn][3] = (col0+1 > r1) ? -1e30f : s[fn][3]*scale;
            }
        } else {
            #pragma unroll
            for (int fn = 0; fn < 16; fn++) {
                s[fn][0]*=scale; s[fn][1]*=scale; s[fn][2]*=scale; s[fn][3]*=scale;
            }
        }

        // ---- online softmax in log2 domain ----
        float m0 = -1e30f, m1 = -1e30f;
        #pragma unroll
        for (int fn = 0; fn < 16; fn++) {
            m0 = fmaxf(m0, fmaxf(s[fn][0], s[fn][1]));
            m1 = fmaxf(m1, fmaxf(s[fn][2], s[fn][3]));
        }
        m0 = fmaxf(m0, __shfl_xor_sync(0xffffffffu, m0, 1));
        m0 = fmaxf(m0, __shfl_xor_sync(0xffffffffu, m0, 2));
        m1 = fmaxf(m1, __shfl_xor_sync(0xffffffffu, m1, 1));
        m1 = fmaxf(m1, __shfl_xor_sync(0xffffffffu, m1, 2));
        const float mn0 = fmaxf(mr0, m0), mn1 = fmaxf(mr1, m1);
        const float cr0 = exp2f(mr0 - mn0), cr1 = exp2f(mr1 - mn1);
        mr0 = mn0; mr1 = mn1;
        l0 *= cr0; l1 *= cr1;
        #pragma unroll
        for (int fn = 0; fn < 16; fn++) {
            ctx[fn][0]*=cr0; ctx[fn][1]*=cr0; ctx[fn][2]*=cr1; ctx[fn][3]*=cr1;
        }
        float ps0 = 0.f, ps1 = 0.f;
        #pragma unroll
        for (int fn = 0; fn < 16; fn++) {
            float p0v = exp2f(s[fn][0]-mn0), p1v = exp2f(s[fn][1]-mn0);
            float p2v = exp2f(s[fn][2]-mn1), p3v = exp2f(s[fn][3]-mn1);
            s[fn][0]=p0v; s[fn][1]=p1v; s[fn][2]=p2v; s[fn][3]=p3v;
            ps0 += p0v + p1v; ps1 += p2v + p3v;
        }
        ps0 += __shfl_xor_sync(0xffffffffu, ps0, 1);
        ps0 += __shfl_xor_sync(0xffffffffu, ps0, 2);
        ps1 += __shfl_xor_sync(0xffffffffu, ps1, 1);
        ps1 += __shfl_xor_sync(0xffffffffu, ps1, 2);
        l0 += ps0; l1 += ps1;

        // ---- wait for V_tt only now ----
        if (has_next) cp_wait<2>();
        else          cp_wait<0>();
        __syncthreads();

        // ---- ctx += P @ V (split-2 on P; S C-frags are PV A-frags) ----
        const uint32_t vb = kb + 32768u;
        #pragma unroll
        for (int kf = 0; kf < 8; kf++) {
            uint32_t ahi[4], alo[4];
            split_pack(s[2*kf][0],   s[2*kf][1],   ahi[0], alo[0]);
            split_pack(s[2*kf][2],   s[2*kf][3],   ahi[1], alo[1]);
            split_pack(s[2*kf+1][0], s[2*kf+1][1], ahi[2], alo[2]);
            split_pack(s[2*kf+1][2], s[2*kf+1][3], ahi[3], alo[3]);
            const int t = kf*16 + t0l;
            #pragma unroll
            for (int f2 = 0; f2 < 8; f2++) {
                uint32_t bb[4];
                ldsm4t(bb, vb + (uint32_t)(t * 256
                                           + (((f2*2 + hi16) ^ (t & 7)) << 4)));
                mma16816(ctx[2*f2],   ahi, bb);   mma16816(ctx[2*f2],   alo, bb);
                mma16816(ctx[2*f2+1], ahi, bb+2); mma16816(ctx[2*f2+1], alo, bb+2);
            }
        }
    }

    // ---- epilogue: normalize and store split ctx ----
    const float inv0 = 1.0f / l0, inv1 = 1.0f / l1;
    const size_t base = ((size_t)b*SEQ + (size_t)st*128 + w*16 + g) * HID + (size_t)n*HDIM;
    #pragma unroll
    for (int fn = 0; fn < 16; fn++) {
        const int col = fn*8 + 2*c;
        st_split2(c0, c1, base + col,           ctx[fn][0]*inv0, ctx[fn][1]*inv0);
        st_split2(c0, c1, base + 8*HID + col,   ctx[fn][2]*inv1, ctx[fn][3]*inv1);
    }
}

// ---------------------------------------------------------------------------
// Host side
// ---------------------------------------------------------------------------
static float* symaddrf(const void* sym) {
    void* p = nullptr; cudaGetSymbolAddress(&p, sym); return (float*)p;
}
static fp16* symaddrh(const void* sym) {
    void* p = nullptr; cudaGetSymbolAddress(&p, sym); return (fp16*)p;
}

extern "C" void kernel_launch(void* const* d_in, const int* in_sizes, int n_in,
                              void* d_out, int out_size)
{
    const float* hidden  = (const float*)d_in[0];
    const float* qkv_w   = (const float*)d_in[2];
    const float* qkv_b   = (const float*)d_in[3];
    const float* dense_w = (const float*)d_in[4];
    const float* dense_b = (const float*)d_in[5];
    const float* mlp_w1  = (const float*)d_in[6];
    const float* mlp_b1  = (const float*)d_in[7];
    const float* mlp_w2  = (const float*)d_in[8];
    const float* mlp_b2  = (const float*)d_in[9];
    const float* ln_in_g   = (const float*)d_in[10];
    const float* ln_in_b   = (const float*)d_in[11];
    const float* ln_post_g = (const float*)d_in[12];
    const float* ln_post_b = (const float*)d_in[13];
    const float* ln_s1_g   = (const float*)d_in[14];
    const float* ln_s1_b   = (const float*)d_in[15];
    const float* ln_s2_g   = (const float*)d_in[16];
    const float* ln_s2_b   = (const float*)d_in[17];

    cudaFuncSetAttribute(k_gemm<0,0>, cudaFuncAttributeMaxDynamicSharedMemorySize, GEMM_SMEM_DYN);
    cudaFuncSetAttribute(k_gemm<0,1>, cudaFuncAttributeMaxDynamicSharedMemorySize, GEMM_SMEM_DYN);
    cudaFuncSetAttribute(k_gemm<1,1>, cudaFuncAttributeMaxDynamicSharedMemorySize, GEMM_SMEM_DYN);
    cudaFuncSetAttribute(k_attn,      cudaFuncAttributeMaxDynamicSharedMemorySize, ATT_SMEM);

    float* h   = symaddrf(g_h);
    float* att = symaddrf(g_att);
    float* h2  = symaddrf(g_h2);
    float* m2  = symaddrf(g_m2);
    fp16* a0 = symaddrh(g_a0);   fp16* a1 = symaddrh(g_a1);
    fp16* q0 = symaddrh(g_qkv0); fp16* q1 = symaddrh(g_qkv1);
    fp16* c0 = symaddrh(g_c0);   fp16* c1 = symaddrh(g_c1);
    fp16* m1h = symaddrh(g_m1h); fp16* m1l = symaddrh(g_m1l);
    fp16* wq = symaddrh(g_wq);
    fp16* wd = symaddrh(g_wd);
    fp16* w1 = symaddrh(g_w1);
    fp16* w2 = symaddrh(g_w2);
    float* out = (float*)d_out;

    // ---- parallel branch: all weight converts on a side stream -------------
    cudaStream_t s1;
    cudaStreamCreateWithFlags(&s1, cudaStreamNonBlocking);
    cudaEvent_t evFork;
    cudaEventCreateWithFlags(&evFork, cudaEventDisableTiming);
    cudaEvent_t evW[LAYERS][4];
    for (int l = 0; l < LAYERS; l++)
        for (int k = 0; k < 4; k++)
            cudaEventCreateWithFlags(&evW[l][k], cudaEventDisableTiming);

    cudaEventRecord(evFork, 0);
    cudaStreamWaitEvent(s1, evFork, 0);
    for (int l = 0; l < LAYERS; l++) {
        {   size_t n = (size_t)H3 * HID; int n4 = (int)(n / 4);
            conv_fp32_fp16<<<(n4 + 255) / 256, 256, 0, s1>>>(
                qkv_w + (size_t)l * n, wq + (size_t)l * n, n4);
            cudaEventRecord(evW[l][0], s1); }
        {   size_t n = (size_t)HID * HID; int n4 = (int)(n / 4);
            conv_fp32_fp16<<<(n4 + 255) / 256, 256, 0, s1>>>(
                dense_w + (size_t)l * n, wd + (size_t)l * n, n4);
            cudaEventRecord(evW[l][1], s1); }
        {   size_t n = (size_t)H4 * HID; int n4 = (int)(n / 4);
            conv_fp32_fp16<<<(n4 + 255) / 256, 256, 0, s1>>>(
                mlp_w1 + (size_t)l * n, w1 + (size_t)l * n, n4);
            cudaEventRecord(evW[l][2], s1); }
        {   size_t n = (size_t)HID * H4; int n4 = (int)(n / 4);
            conv_fp32_fp16<<<(n4 + 255) / 256, 256, 0, s1>>>(
                mlp_w2 + (size_t)l * n, w2 + (size_t)l * n, n4);
            cudaEventRecord(evW[l][3], s1); }
    }

    // ---- main stream --------------------------------------------------------
    ln_split_kernel<<<ROWS, 256>>>(hidden, ln_in_g, ln_in_b, a0, a1);

    for (int l = 0; l < LAYERS; l++) {
        const float* hin = (l == 0) ? hidden : h;
        const float* l_qkv_b   = qkv_b   + (size_t)l * H3;
        const float* l_dense_b = dense_b + (size_t)l * HID;
        const float* l_b1 = mlp_b1 + (size_t)l * H4;
        const float* l_b2 = mlp_b2 + (size_t)l * HID;
        const fp16* l_wq = wq + (size_t)l * H3 * HID;
        const fp16* l_wd = wd + (size_t)l * HID * HID;
        const fp16* l_w1 = w1 + (size_t)l * H4 * HID;
        const fp16* l_w2 = w2 + (size_t)l * HID * H4;

        // qkv: full split-2 compute; K/V columns hi-only store
        cudaStreamWaitEvent(0, evW[l][0], 0);
        k_gemm<0,1><<<dim3(H3/128, ROWS/128), 256, GEMM_SMEM_DYN>>>(
            a0, a1, l_wq, l_qkv_b, nullptr, q0, q1, ROWS, H3, HID, HID);

        // fused flash attention -> split ctx (heavy tiles first, all heads)
        k_attn<<<512, 256, ATT_SMEM>>>(q0, q1, c0, c1);

        // attn_out = ctx @ dense_w^T + b  (fp32)
        cudaStreamWaitEvent(0, evW[l][1], 0);
        k_gemm<0,0><<<dim3(HID/128, ROWS/128), 256, GEMM_SMEM_DYN>>>(
            c0, c1, l_wd, l_dense_b, att, nullptr, nullptr, ROWS, HID, HID, 0);

        // h2 = hin + LN_s1(att); a0/a1 = split(LN_post(h2))
        ln_res_split_kernel<1><<<ROWS, 256>>>(
            att, hin, ln_s1_g + l*HID, ln_s1_b + l*HID,
            ln_post_g + l*HID, ln_post_b + l*HID, h2, a0, a1);

        // m1 = gelu(y @ w1^T + b1) -> split (full split everywhere)
        cudaStreamWaitEvent(0, evW[l][2], 0);
        k_gemm<1,1><<<dim3(H4/128, ROWS/128), 256, GEMM_SMEM_DYN>>>(
            a0, a1, l_w1, l_b1, nullptr, m1h, m1l, ROWS, H4, HID, H4);

        // m2 = m1 @ w2^T + b2 (fp32)
        cudaStreamWaitEvent(0, evW[l][3], 0);
        k_gemm<0,0><<<dim3(HID/128, ROWS/128), 256, GEMM_SMEM_DYN>>>(
            m1h, m1l, l_w2, l_b2, m2, nullptr, nullptr, ROWS, HID, H4, 0);

        if (l + 1 < LAYERS) {
            ln_res_split_kernel<1><<<ROWS, 256>>>(
                m2, h2, ln_s2_g + l*HID, ln_s2_b + l*HID,
                ln_in_g + (l+1)*HID, ln_in_b + (l+1)*HID, h, a0, a1);
        } else {
            ln_res_split_kernel<0><<<ROWS, 256>>>(
                m2, h2, ln_s2_g + l*HID, ln_s2_b + l*HID,
                nullptr, nullptr, out, nullptr, nullptr);
        }
    }
}